// round 3
// baseline (speedup 1.0000x reference)
#include <cuda_runtime.h>
#include <cuda_bf16.h>
#include <math_constants.h>

// Problem constants
#define NB    8
#define NS    1024
#define NF    512
#define NHID  1024
#define NH    8
#define NDK   64
#define NM    (NB * NS)        // 8192 token rows

// Scratch (allocation-free: __device__ globals)
__device__ float g_h [NM * NHID];            // 32 MB  relu(q@w1+b1)
__device__ float g_aw[NB * NH * NS * NDK];   // 16 MB  [B,H,S,dk]
__device__ float g_v [NB * NH * NS * NDK];   // 16 MB  [B,H,S,dk]
__device__ float g_x [NM * NF];              // 16 MB  [B,S,F]

// ---------------------------------------------------------------------------
// Tiled SGEMM: C = epilogue(A[M,K] @ W[K,N] + bias[N])
// BM=BN=128, BK=16, 256 threads, 8x8 per thread. 16 KB static smem.
// MODE 0: relu(acc+bias) -> row-major [M,N]
// MODE 1: acc+bias       -> scatter to [B,H,S,dk] head layout
// MODE 2: acc+bias       -> row-major [M,N]
// All dims are multiples of tile sizes for this problem.
// ---------------------------------------------------------------------------
template <int MODE>
__global__ void __launch_bounds__(256)
sgemm_kernel(int M, int N, int K,
             const float* __restrict__ A,
             const float* __restrict__ W,
             const float* __restrict__ bias,
             float* __restrict__ out)
{
    constexpr int BM = 128, BN = 128, BK = 16;
    __shared__ float As[BK][BM];   // transposed A tile
    __shared__ float Bs[BK][BN];

    const int tid = threadIdx.x;
    const int bm  = blockIdx.y * BM;
    const int bn  = blockIdx.x * BN;

    const int tr = tid >> 4;   // 0..15 -> row group of 8
    const int tc = tid & 15;   // 0..15 -> col group of 8

    const int arow = tid >> 2;  // 0..63, A tile: 128 rows x 4 float4-cols
    const int acol = tid & 3;
    const int brow = tid >> 5;  // 0..7,  B tile: 16 rows x 32 float4-cols
    const int bcol = tid & 31;

    float acc[8][8];
#pragma unroll
    for (int i = 0; i < 8; i++)
#pragma unroll
        for (int j = 0; j < 8; j++) acc[i][j] = 0.f;

    for (int k0 = 0; k0 < K; k0 += BK) {
#pragma unroll
        for (int l = 0; l < 2; l++) {
            const int r = arow + l * 64;
            const float4 va = *reinterpret_cast<const float4*>(
                &A[(size_t)(bm + r) * K + k0 + acol * 4]);
            As[acol * 4 + 0][r] = va.x;
            As[acol * 4 + 1][r] = va.y;
            As[acol * 4 + 2][r] = va.z;
            As[acol * 4 + 3][r] = va.w;
        }
#pragma unroll
        for (int l = 0; l < 2; l++) {
            const int r = brow + l * 8;
            *reinterpret_cast<float4*>(&Bs[r][bcol * 4]) =
                *reinterpret_cast<const float4*>(&W[(size_t)(k0 + r) * N + bn + bcol * 4]);
        }
        __syncthreads();

#pragma unroll
        for (int k = 0; k < BK; k++) {
            float ra[8], rb[8];
#pragma unroll
            for (int i = 0; i < 8; i++) ra[i] = As[k][tr * 8 + i];
#pragma unroll
            for (int j = 0; j < 8; j++) rb[j] = Bs[k][tc * 8 + j];
#pragma unroll
            for (int i = 0; i < 8; i++)
#pragma unroll
                for (int j = 0; j < 8; j++) acc[i][j] += ra[i] * rb[j];
        }
        __syncthreads();
    }

#pragma unroll
    for (int i = 0; i < 8; i++) {
        const int m = bm + tr * 8 + i;
#pragma unroll
        for (int j = 0; j < 8; j++) {
            const int n = bn + tc * 8 + j;
            float val = acc[i][j] + bias[n];
            if (MODE == 0) {
                val = fmaxf(val, 0.f);
                out[(size_t)m * N + n] = val;
            } else if (MODE == 1) {
                const int b = m >> 10, s = m & 1023;
                const int h = n >> 6,  d = n & 63;
                out[((((size_t)b * NH + h) * NS + s) * NDK) + d] = val;
            } else {
                out[(size_t)m * N + n] = val;
            }
        }
    }
}

// ---------------------------------------------------------------------------
// Fused attention: for each (b,h): scores = aw@aw^T / 8 ; softmax ; @ v
// Flash-style: 64-query tile per CTA, stream 32-key tiles, online softmax.
// Static shared memory only (~42 KB) -> no cudaFuncSetAttribute needed.
// 256 threads as a 16x16 grid:
//   S phase  (64q x 32k): each thread 4 rows x 2 cols
//   O phase  (64q x 64d): each thread 4 rows x 4 cols
// ---------------------------------------------------------------------------
__global__ void __launch_bounds__(256)
attn_kernel(const float* __restrict__ aw,
            const float* __restrict__ vv,
            float* __restrict__ x)
{
    __shared__ float Qs [64][65];   // Q rows      (r, d)   16,640 B
    __shared__ float Kst[64][33];   // K transpose (d, c)    8,448 B
    __shared__ float Vs [32][65];   // V rows      (c, d)    8,320 B
    __shared__ float Ps [64][33];   // softmax P   (r, c)    8,448 B

    const int tid = threadIdx.x;
    const int tx  = tid & 15;         // column group
    const int ty  = tid >> 4;         // row group (4 rows each)
    const int bh  = blockIdx.y;       // 0..63 = b*8+h
    const int q0  = blockIdx.x * 64;

    const float* Abh = aw + (size_t)bh * NS * NDK;
    const float* Vbh = vv + (size_t)bh * NS * NDK;

    // Load Q tile: 64 rows x 64 cols, float4 loads (1024 float4 / 256 thr)
    for (int i = tid; i < 64 * 16; i += 256) {
        const int r = i >> 4, d4 = (i & 15) * 4;
        const float4 q4 = *reinterpret_cast<const float4*>(
            &Abh[(size_t)(q0 + r) * NDK + d4]);
        Qs[r][d4 + 0] = q4.x; Qs[r][d4 + 1] = q4.y;
        Qs[r][d4 + 2] = q4.z; Qs[r][d4 + 3] = q4.w;
    }

    float mrow[4], lrow[4], acc[4][4];
#pragma unroll
    for (int i = 0; i < 4; i++) {
        mrow[i] = -CUDART_INF_F;
        lrow[i] = 0.f;
#pragma unroll
        for (int j = 0; j < 4; j++) acc[i][j] = 0.f;
    }
    __syncthreads();

    for (int k0 = 0; k0 < NS; k0 += 32) {
        // Load K tile (transposed into Kst[d][c]) and V tile: 32 rows x 64 cols
        for (int i = tid; i < 32 * 16; i += 256) {
            const int c = i >> 4, d4 = (i & 15) * 4;
            const float4 k4 = *reinterpret_cast<const float4*>(
                &Abh[(size_t)(k0 + c) * NDK + d4]);
            Kst[d4 + 0][c] = k4.x;
            Kst[d4 + 1][c] = k4.y;
            Kst[d4 + 2][c] = k4.z;
            Kst[d4 + 3][c] = k4.w;
            const float4 v4 = *reinterpret_cast<const float4*>(
                &Vbh[(size_t)(k0 + c) * NDK + d4]);
            Vs[c][d4 + 0] = v4.x; Vs[c][d4 + 1] = v4.y;
            Vs[c][d4 + 2] = v4.z; Vs[c][d4 + 3] = v4.w;
        }
        __syncthreads();

        // S = Q @ K^T * 0.125   (64q x 32k; 4x2 per thread)
        float s[4][2];
#pragma unroll
        for (int i = 0; i < 4; i++) { s[i][0] = 0.f; s[i][1] = 0.f; }

        for (int d = 0; d < 64; d++) {
            float qa[4], kb[2];
#pragma unroll
            for (int i = 0; i < 4; i++) qa[i] = Qs[ty * 4 + i][d];
            kb[0] = Kst[d][tx * 2 + 0];
            kb[1] = Kst[d][tx * 2 + 1];
#pragma unroll
            for (int i = 0; i < 4; i++) {
                s[i][0] += qa[i] * kb[0];
                s[i][1] += qa[i] * kb[1];
            }
        }

        // Online softmax per query row (16 lanes of a warp-half share a row)
#pragma unroll
        for (int i = 0; i < 4; i++) {
            float rm = -CUDART_INF_F;
#pragma unroll
            for (int j = 0; j < 2; j++) {
                s[i][j] *= 0.125f;
                rm = fmaxf(rm, s[i][j]);
            }
#pragma unroll
            for (int o = 8; o > 0; o >>= 1)
                rm = fmaxf(rm, __shfl_xor_sync(0xffffffffu, rm, o));

            const float mnew  = fmaxf(mrow[i], rm);
            const float alpha = __expf(mrow[i] - mnew);
            float psum = 0.f;
#pragma unroll
            for (int j = 0; j < 2; j++) {
                s[i][j] = __expf(s[i][j] - mnew);
                psum += s[i][j];
            }
#pragma unroll
            for (int o = 8; o > 0; o >>= 1)
                psum += __shfl_xor_sync(0xffffffffu, psum, o);

            lrow[i] = lrow[i] * alpha + psum;
            mrow[i] = mnew;
#pragma unroll
            for (int j = 0; j < 4; j++) acc[i][j] *= alpha;
        }

        // Stage P, then O += P @ V  (64x32 @ 32x64; 4x4 per thread)
#pragma unroll
        for (int i = 0; i < 4; i++) {
            Ps[ty * 4 + i][tx * 2 + 0] = s[i][0];
            Ps[ty * 4 + i][tx * 2 + 1] = s[i][1];
        }
        __syncthreads();

        for (int c = 0; c < 32; c++) {
            float pa[4], vb[4];
#pragma unroll
            for (int i = 0; i < 4; i++) pa[i] = Ps[ty * 4 + i][c];
#pragma unroll
            for (int j = 0; j < 4; j++) vb[j] = Vs[c][tx * 4 + j];
#pragma unroll
            for (int i = 0; i < 4; i++)
#pragma unroll
                for (int j = 0; j < 4; j++) acc[i][j] += pa[i] * vb[j];
        }
        __syncthreads();
    }

    // Write out: x[b, s, h*64+d]
    const int b = bh >> 3, h = bh & 7;
#pragma unroll
    for (int i = 0; i < 4; i++) {
        const int srow = q0 + ty * 4 + i;
        const float inv = 1.f / lrow[i];
#pragma unroll
        for (int j = 0; j < 4; j++) {
            const int d = tx * 4 + j;
            x[((size_t)(b * NS + srow)) * NF + h * NDK + d] = acc[i][j] * inv;
        }
    }
}

// ---------------------------------------------------------------------------
extern "C" void kernel_launch(void* const* d_in, const int* in_sizes, int n_in,
                              void* d_out, int out_size)
{
    const float* query = (const float*)d_in[0];
    // d_in[1] = key_t (unused by the synthesizer module)
    const float* value = (const float*)d_in[2];
    const float* w1 = (const float*)d_in[3];
    const float* b1 = (const float*)d_in[4];
    const float* w2 = (const float*)d_in[5];
    const float* b2 = (const float*)d_in[6];
    const float* wv = (const float*)d_in[7];
    const float* bv = (const float*)d_in[8];
    const float* wo = (const float*)d_in[9];
    const float* bo = (const float*)d_in[10];
    float* out = (float*)d_out;

    float *ph, *paw, *pv, *px;
    cudaGetSymbolAddress((void**)&ph,  g_h);
    cudaGetSymbolAddress((void**)&paw, g_aw);
    cudaGetSymbolAddress((void**)&pv,  g_v);
    cudaGetSymbolAddress((void**)&px,  g_x);

    const dim3 blk(256);

    // 1) h = relu(q @ w1 + b1)          [8192,1024]
    sgemm_kernel<0><<<dim3(NHID / 128, NM / 128), blk>>>(NM, NHID, NF, query, w1, b1, ph);
    // 2) aw = h @ w2 + b2 -> [B,H,S,dk]
    sgemm_kernel<1><<<dim3(NF / 128, NM / 128), blk>>>(NM, NF, NHID, ph, w2, b2, paw);
    // 3) v = value @ wv + bv -> [B,H,S,dk]
    sgemm_kernel<1><<<dim3(NF / 128, NM / 128), blk>>>(NM, NF, NF, value, wv, bv, pv);
    // 4) fused attention -> x [B,S,F]
    attn_kernel<<<dim3(NS / 64, NB * NH), blk>>>(paw, pv, px);
    // 5) out = x @ wo + bo
    sgemm_kernel<2><<<dim3(NF / 128, NM / 128), blk>>>(NM, NF, NF, px, wo, bo, out);
}

// round 5
// speedup vs baseline: 1.2213x; 1.2213x over previous
#include <cuda_runtime.h>
#include <cuda_bf16.h>
#include <math_constants.h>
#include <cstdint>

// Problem constants
#define NB    8
#define NS    1024
#define NF    512
#define NHID  1024
#define NH    8
#define NDK   64
#define NM    (NB * NS)        // 8192 token rows

// Scratch (allocation-free: __device__ globals)
__device__ float g_h [NM * NHID];            // 32 MB  relu(q@w1+b1)
__device__ float g_aw[NB * NH * NS * NDK];   // 16 MB  [B,H,S,dk]
__device__ float g_v [NB * NH * NS * NDK];   // 16 MB  [B,H,S,dk]
__device__ float g_x [NM * NF];              // 16 MB  [B,S,F]

__device__ __forceinline__ uint32_t f2tf32(float f) {
    uint32_t u;
    asm("cvt.rna.tf32.f32 %0, %1;" : "=r"(u) : "f"(f));
    return u;
}

// ---------------------------------------------------------------------------
// TF32 tensor-core GEMM: C = epilogue(A[M,K] @ W[K,N] + bias[N])
// CTA tile 128x128, BK=32. 256 threads = 8 warps (2 x 4), warp tile 64x32.
// mma.sync.m16n8k8.tf32, fp32 accumulate.
// Smem layout pairs (k, k+4) adjacently so each A/B fragment pair is 1 LDS.64:
//   col_s(k) = (k & ~7) + 2*(k & 3) + ((k >> 2) & 1)
// MODE 0: relu(acc+bias) -> row-major [M,N]
// MODE 1: acc+bias       -> scatter to [B,H,S,dk] head layout
// MODE 2: acc+bias       -> row-major [M,N]
// ---------------------------------------------------------------------------
template <int MODE>
__global__ void __launch_bounds__(256)
mma_gemm(int M, int N, int K,
         const float* __restrict__ A,
         const float* __restrict__ W,
         const float* __restrict__ bias,
         float* __restrict__ out)
{
    constexpr int BM = 128, BN = 128, BK = 32;
    constexpr int LDA = BK + 2;   // 34: pad to kill row-stride bank conflicts
    __shared__ uint32_t As2[BM][LDA];   // [m][col_s(k)]
    __shared__ uint32_t Bs2[BN][LDA];   // [n][col_s(k)]  (W transposed per-tile)

    const int tid  = threadIdx.x;
    const int bm   = blockIdx.y * BM;
    const int bn   = blockIdx.x * BN;
    const int wid  = tid >> 5;
    const int lane = tid & 31;
    const int wr   = wid & 1;    // warp row: 2 x 64
    const int wc   = wid >> 1;   // warp col: 4 x 32
    const int lrow = lane >> 2;  // 0..7
    const int lcol = lane & 3;   // 0..3

    float c[4][4][4];
#pragma unroll
    for (int mf = 0; mf < 4; mf++)
#pragma unroll
        for (int nf = 0; nf < 4; nf++)
#pragma unroll
            for (int r = 0; r < 4; r++) c[mf][nf][r] = 0.f;

    for (int k0 = 0; k0 < K; k0 += BK) {
        // --- A tile: 128 rows x 32 k (8 float4 per row), 4 float4/thread ---
#pragma unroll
        for (int i = 0; i < 4; i++) {
            const int idx = tid + i * 256;
            const int row = idx >> 3, c4 = idx & 7;
            const float4 v = *reinterpret_cast<const float4*>(
                &A[(size_t)(bm + row) * K + k0 + c4 * 4]);
            const int kl = c4 * 4;
            const float vv[4] = {v.x, v.y, v.z, v.w};
#pragma unroll
            for (int e = 0; e < 4; e++) {
                const int k = kl + e;
                const int cs = (k & ~7) + 2 * (k & 3) + ((k >> 2) & 1);
                As2[row][cs] = f2tf32(vv[e]);
            }
        }
        // --- W tile: 32 k-rows x 128 n (32 float4 per row), transposed ---
#pragma unroll
        for (int i = 0; i < 4; i++) {
            const int idx = tid + i * 256;
            const int kr = idx >> 5, n4 = idx & 31;
            const float4 v = *reinterpret_cast<const float4*>(
                &W[(size_t)(k0 + kr) * N + bn + n4 * 4]);
            const int cs = (kr & ~7) + 2 * (kr & 3) + ((kr >> 2) & 1);
            const float vv[4] = {v.x, v.y, v.z, v.w};
#pragma unroll
            for (int e = 0; e < 4; e++)
                Bs2[n4 * 4 + e][cs] = f2tf32(vv[e]);
        }
        __syncthreads();

#pragma unroll
        for (int kb = 0; kb < BK; kb += 8) {
            // A fragments: 4 m-frags, each (a0,a2) and (a1,a3) via LDS.64
            uint32_t af[4][4];
#pragma unroll
            for (int mf = 0; mf < 4; mf++) {
                const int m = wr * 64 + mf * 16 + lrow;
                const uint2 p0 = *reinterpret_cast<const uint2*>(&As2[m][kb + 2 * lcol]);
                const uint2 p1 = *reinterpret_cast<const uint2*>(&As2[m + 8][kb + 2 * lcol]);
                af[mf][0] = p0.x; af[mf][2] = p0.y;   // (row,   k), (row,   k+4)
                af[mf][1] = p1.x; af[mf][3] = p1.y;   // (row+8, k), (row+8, k+4)
            }
            // B fragments: 4 n-frags, (b0,b1) via LDS.64
            uint32_t bf[4][2];
#pragma unroll
            for (int nf = 0; nf < 4; nf++) {
                const int n = wc * 32 + nf * 8 + lrow;
                const uint2 q = *reinterpret_cast<const uint2*>(&Bs2[n][kb + 2 * lcol]);
                bf[nf][0] = q.x; bf[nf][1] = q.y;     // (k, n), (k+4, n)
            }
#pragma unroll
            for (int mf = 0; mf < 4; mf++)
#pragma unroll
                for (int nf = 0; nf < 4; nf++) {
                    asm volatile(
                        "mma.sync.aligned.m16n8k8.row.col.f32.tf32.tf32.f32 "
                        "{%0,%1,%2,%3}, {%4,%5,%6,%7}, {%8,%9}, {%0,%1,%2,%3};"
                        : "+f"(c[mf][nf][0]), "+f"(c[mf][nf][1]),
                          "+f"(c[mf][nf][2]), "+f"(c[mf][nf][3])
                        : "r"(af[mf][0]), "r"(af[mf][1]), "r"(af[mf][2]), "r"(af[mf][3]),
                          "r"(bf[nf][0]), "r"(bf[nf][1]));
                }
        }
        __syncthreads();
    }

    // Epilogue: c0,c1 -> (row, col), (row, col+1); c2,c3 -> row+8
#pragma unroll
    for (int mf = 0; mf < 4; mf++) {
#pragma unroll
        for (int nf = 0; nf < 4; nf++) {
            const int row0 = bm + wr * 64 + mf * 16 + lrow;
            const int col0 = bn + wc * 32 + nf * 8 + 2 * lcol;
            const float bsum0 = bias[col0], bsum1 = bias[col0 + 1];
#pragma unroll
            for (int half = 0; half < 2; half++) {
                const int m = row0 + half * 8;
                float v0 = c[mf][nf][half * 2 + 0] + bsum0;
                float v1 = c[mf][nf][half * 2 + 1] + bsum1;
                if (MODE == 0) { v0 = fmaxf(v0, 0.f); v1 = fmaxf(v1, 0.f); }
                if (MODE == 1) {
                    const int b = m >> 10, s = m & 1023;
                    const int h = col0 >> 6, d = col0 & 63;   // col0 even, d<=62
                    *reinterpret_cast<float2*>(
                        &out[((((size_t)b * NH + h) * NS + s) * NDK) + d]) =
                        make_float2(v0, v1);
                } else {
                    *reinterpret_cast<float2*>(&out[(size_t)m * N + col0]) =
                        make_float2(v0, v1);
                }
            }
        }
    }
}

// ---------------------------------------------------------------------------
// Fused attention (unchanged from passing round-3 kernel)
// ---------------------------------------------------------------------------
__global__ void __launch_bounds__(256)
attn_kernel(const float* __restrict__ aw,
            const float* __restrict__ vv,
            float* __restrict__ x)
{
    __shared__ float Qs [64][65];
    __shared__ float Kst[64][33];
    __shared__ float Vs [32][65];
    __shared__ float Ps [64][33];

    const int tid = threadIdx.x;
    const int tx  = tid & 15;
    const int ty  = tid >> 4;
    const int bh  = blockIdx.y;
    const int q0  = blockIdx.x * 64;

    const float* Abh = aw + (size_t)bh * NS * NDK;
    const float* Vbh = vv + (size_t)bh * NS * NDK;

    for (int i = tid; i < 64 * 16; i += 256) {
        const int r = i >> 4, d4 = (i & 15) * 4;
        const float4 q4 = *reinterpret_cast<const float4*>(
            &Abh[(size_t)(q0 + r) * NDK + d4]);
        Qs[r][d4 + 0] = q4.x; Qs[r][d4 + 1] = q4.y;
        Qs[r][d4 + 2] = q4.z; Qs[r][d4 + 3] = q4.w;
    }

    float mrow[4], lrow[4], acc[4][4];
#pragma unroll
    for (int i = 0; i < 4; i++) {
        mrow[i] = -CUDART_INF_F;
        lrow[i] = 0.f;
#pragma unroll
        for (int j = 0; j < 4; j++) acc[i][j] = 0.f;
    }
    __syncthreads();

    for (int k0 = 0; k0 < NS; k0 += 32) {
        for (int i = tid; i < 32 * 16; i += 256) {
            const int c = i >> 4, d4 = (i & 15) * 4;
            const float4 k4 = *reinterpret_cast<const float4*>(
                &Abh[(size_t)(k0 + c) * NDK + d4]);
            Kst[d4 + 0][c] = k4.x;
            Kst[d4 + 1][c] = k4.y;
            Kst[d4 + 2][c] = k4.z;
            Kst[d4 + 3][c] = k4.w;
            const float4 v4 = *reinterpret_cast<const float4*>(
                &Vbh[(size_t)(k0 + c) * NDK + d4]);
            Vs[c][d4 + 0] = v4.x; Vs[c][d4 + 1] = v4.y;
            Vs[c][d4 + 2] = v4.z; Vs[c][d4 + 3] = v4.w;
        }
        __syncthreads();

        float s[4][2];
#pragma unroll
        for (int i = 0; i < 4; i++) { s[i][0] = 0.f; s[i][1] = 0.f; }

        for (int d = 0; d < 64; d++) {
            float qa[4], kb[2];
#pragma unroll
            for (int i = 0; i < 4; i++) qa[i] = Qs[ty * 4 + i][d];
            kb[0] = Kst[d][tx * 2 + 0];
            kb[1] = Kst[d][tx * 2 + 1];
#pragma unroll
            for (int i = 0; i < 4; i++) {
                s[i][0] += qa[i] * kb[0];
                s[i][1] += qa[i] * kb[1];
            }
        }

#pragma unroll
        for (int i = 0; i < 4; i++) {
            float rm = -CUDART_INF_F;
#pragma unroll
            for (int j = 0; j < 2; j++) {
                s[i][j] *= 0.125f;
                rm = fmaxf(rm, s[i][j]);
            }
#pragma unroll
            for (int o = 8; o > 0; o >>= 1)
                rm = fmaxf(rm, __shfl_xor_sync(0xffffffffu, rm, o));

            const float mnew  = fmaxf(mrow[i], rm);
            const float alpha = __expf(mrow[i] - mnew);
            float psum = 0.f;
#pragma unroll
            for (int j = 0; j < 2; j++) {
                s[i][j] = __expf(s[i][j] - mnew);
                psum += s[i][j];
            }
#pragma unroll
            for (int o = 8; o > 0; o >>= 1)
                psum += __shfl_xor_sync(0xffffffffu, psum, o);

            lrow[i] = lrow[i] * alpha + psum;
            mrow[i] = mnew;
#pragma unroll
            for (int j = 0; j < 4; j++) acc[i][j] *= alpha;
        }

#pragma unroll
        for (int i = 0; i < 4; i++) {
            Ps[ty * 4 + i][tx * 2 + 0] = s[i][0];
            Ps[ty * 4 + i][tx * 2 + 1] = s[i][1];
        }
        __syncthreads();

        for (int c = 0; c < 32; c++) {
            float pa[4], vb[4];
#pragma unroll
            for (int i = 0; i < 4; i++) pa[i] = Ps[ty * 4 + i][c];
#pragma unroll
            for (int j = 0; j < 4; j++) vb[j] = Vs[c][tx * 4 + j];
#pragma unroll
            for (int i = 0; i < 4; i++)
#pragma unroll
                for (int j = 0; j < 4; j++) acc[i][j] += pa[i] * vb[j];
        }
        __syncthreads();
    }

    const int b = bh >> 3, h = bh & 7;
#pragma unroll
    for (int i = 0; i < 4; i++) {
        const int srow = q0 + ty * 4 + i;
        const float inv = 1.f / lrow[i];
#pragma unroll
        for (int j = 0; j < 4; j++) {
            const int d = tx * 4 + j;
            x[((size_t)(b * NS + srow)) * NF + h * NDK + d] = acc[i][j] * inv;
        }
    }
}

// ---------------------------------------------------------------------------
extern "C" void kernel_launch(void* const* d_in, const int* in_sizes, int n_in,
                              void* d_out, int out_size)
{
    const float* query = (const float*)d_in[0];
    // d_in[1] = key_t (unused by the synthesizer module)
    const float* value = (const float*)d_in[2];
    const float* w1 = (const float*)d_in[3];
    const float* b1 = (const float*)d_in[4];
    const float* w2 = (const float*)d_in[5];
    const float* b2 = (const float*)d_in[6];
    const float* wv = (const float*)d_in[7];
    const float* bv = (const float*)d_in[8];
    const float* wo = (const float*)d_in[9];
    const float* bo = (const float*)d_in[10];
    float* out = (float*)d_out;

    float *ph, *paw, *pv, *px;
    cudaGetSymbolAddress((void**)&ph,  g_h);
    cudaGetSymbolAddress((void**)&paw, g_aw);
    cudaGetSymbolAddress((void**)&pv,  g_v);
    cudaGetSymbolAddress((void**)&px,  g_x);

    const dim3 blk(256);

    // 1) h = relu(q @ w1 + b1)          [8192,1024]
    mma_gemm<0><<<dim3(NHID / 128, NM / 128), blk>>>(NM, NHID, NF, query, w1, b1, ph);
    // 2) aw = h @ w2 + b2 -> [B,H,S,dk]
    mma_gemm<1><<<dim3(NF / 128, NM / 128), blk>>>(NM, NF, NHID, ph, w2, b2, paw);
    // 3) v = value @ wv + bv -> [B,H,S,dk]
    mma_gemm<1><<<dim3(NF / 128, NM / 128), blk>>>(NM, NF, NF, value, wv, bv, pv);
    // 4) fused attention -> x [B,S,F]
    attn_kernel<<<dim3(NS / 64, NB * NH), blk>>>(paw, pv, px);
    // 5) out = x @ wo + bo
    mma_gemm<2><<<dim3(NF / 128, NM / 128), blk>>>(NM, NF, NF, px, wo, bo, out);
}

// round 6
// speedup vs baseline: 2.0320x; 1.6638x over previous
#include <cuda_runtime.h>
#include <cuda_bf16.h>
#include <math_constants.h>
#include <cstdint>

// Problem constants
#define NB    8
#define NS    1024
#define NF    512
#define NHID  1024
#define NH    8
#define NDK   64
#define NM    (NB * NS)        // 8192 token rows

// Scratch (allocation-free: __device__ globals)
__device__ float g_h [NM * NHID];            // 32 MB  relu(q@w1+b1)
__device__ float g_aw[NB * NH * NS * NDK];   // 16 MB  [B,H,S,dk]
__device__ float g_v [NB * NH * NS * NDK];   // 16 MB  [B,H,S,dk]
__device__ float g_x [NM * NF];              // 16 MB  [B,S,F]

__device__ __forceinline__ uint32_t f2tf32(float f) {
    uint32_t u;
    asm("cvt.rna.tf32.f32 %0, %1;" : "=r"(u) : "f"(f));
    return u;
}

// smem column pairing: (k, k+4) adjacent so an A/B fragment pair is one LDS.64
__device__ __forceinline__ int csw(int k) {
    return (k & ~7) + 2 * (k & 3) + ((k >> 2) & 1);
}

__device__ __forceinline__ void mma8(float* c,
                                     uint32_t a0, uint32_t a1, uint32_t a2, uint32_t a3,
                                     uint32_t b0, uint32_t b1) {
    asm volatile(
        "mma.sync.aligned.m16n8k8.row.col.f32.tf32.tf32.f32 "
        "{%0,%1,%2,%3}, {%4,%5,%6,%7}, {%8,%9}, {%0,%1,%2,%3};"
        : "+f"(c[0]), "+f"(c[1]), "+f"(c[2]), "+f"(c[3])
        : "r"(a0), "r"(a1), "r"(a2), "r"(a3), "r"(b0), "r"(b1));
}

// ---------------------------------------------------------------------------
// TF32 tensor-core GEMM (unchanged from round-5 passing version)
// ---------------------------------------------------------------------------
template <int MODE>
__global__ void __launch_bounds__(256)
mma_gemm(int M, int N, int K,
         const float* __restrict__ A,
         const float* __restrict__ W,
         const float* __restrict__ bias,
         float* __restrict__ out)
{
    constexpr int BM = 128, BN = 128, BK = 32;
    constexpr int LDA = BK + 2;
    __shared__ uint32_t As2[BM][LDA];
    __shared__ uint32_t Bs2[BN][LDA];

    const int tid  = threadIdx.x;
    const int bm   = blockIdx.y * BM;
    const int bn   = blockIdx.x * BN;
    const int wid  = tid >> 5;
    const int lane = tid & 31;
    const int wr   = wid & 1;
    const int wc   = wid >> 1;
    const int lrow = lane >> 2;
    const int lcol = lane & 3;

    float c[4][4][4];
#pragma unroll
    for (int mf = 0; mf < 4; mf++)
#pragma unroll
        for (int nf = 0; nf < 4; nf++)
#pragma unroll
            for (int r = 0; r < 4; r++) c[mf][nf][r] = 0.f;

    for (int k0 = 0; k0 < K; k0 += BK) {
#pragma unroll
        for (int i = 0; i < 4; i++) {
            const int idx = tid + i * 256;
            const int row = idx >> 3, c4 = idx & 7;
            const float4 v = *reinterpret_cast<const float4*>(
                &A[(size_t)(bm + row) * K + k0 + c4 * 4]);
            const int kl = c4 * 4;
            const float vv[4] = {v.x, v.y, v.z, v.w};
#pragma unroll
            for (int e = 0; e < 4; e++)
                As2[row][csw(kl + e)] = f2tf32(vv[e]);
        }
#pragma unroll
        for (int i = 0; i < 4; i++) {
            const int idx = tid + i * 256;
            const int kr = idx >> 5, n4 = idx & 31;
            const float4 v = *reinterpret_cast<const float4*>(
                &W[(size_t)(k0 + kr) * N + bn + n4 * 4]);
            const int cs = csw(kr);
            const float vv[4] = {v.x, v.y, v.z, v.w};
#pragma unroll
            for (int e = 0; e < 4; e++)
                Bs2[n4 * 4 + e][cs] = f2tf32(vv[e]);
        }
        __syncthreads();

#pragma unroll
        for (int kb = 0; kb < BK; kb += 8) {
            uint32_t af[4][4];
#pragma unroll
            for (int mf = 0; mf < 4; mf++) {
                const int m = wr * 64 + mf * 16 + lrow;
                const uint2 p0 = *reinterpret_cast<const uint2*>(&As2[m][kb + 2 * lcol]);
                const uint2 p1 = *reinterpret_cast<const uint2*>(&As2[m + 8][kb + 2 * lcol]);
                af[mf][0] = p0.x; af[mf][2] = p0.y;
                af[mf][1] = p1.x; af[mf][3] = p1.y;
            }
            uint32_t bf[4][2];
#pragma unroll
            for (int nf = 0; nf < 4; nf++) {
                const int n = wc * 32 + nf * 8 + lrow;
                const uint2 q = *reinterpret_cast<const uint2*>(&Bs2[n][kb + 2 * lcol]);
                bf[nf][0] = q.x; bf[nf][1] = q.y;
            }
#pragma unroll
            for (int mf = 0; mf < 4; mf++)
#pragma unroll
                for (int nf = 0; nf < 4; nf++)
                    mma8(c[mf][nf], af[mf][0], af[mf][1], af[mf][2], af[mf][3],
                         bf[nf][0], bf[nf][1]);
        }
        __syncthreads();
    }

#pragma unroll
    for (int mf = 0; mf < 4; mf++) {
#pragma unroll
        for (int nf = 0; nf < 4; nf++) {
            const int row0 = bm + wr * 64 + mf * 16 + lrow;
            const int col0 = bn + wc * 32 + nf * 8 + 2 * lcol;
            const float bsum0 = bias[col0], bsum1 = bias[col0 + 1];
#pragma unroll
            for (int half = 0; half < 2; half++) {
                const int m = row0 + half * 8;
                float v0 = c[mf][nf][half * 2 + 0] + bsum0;
                float v1 = c[mf][nf][half * 2 + 1] + bsum1;
                if (MODE == 0) { v0 = fmaxf(v0, 0.f); v1 = fmaxf(v1, 0.f); }
                if (MODE == 1) {
                    const int b = m >> 10, s = m & 1023;
                    const int h = col0 >> 6, d = col0 & 63;
                    *reinterpret_cast<float2*>(
                        &out[((((size_t)b * NH + h) * NS + s) * NDK) + d]) =
                        make_float2(v0, v1);
                } else {
                    *reinterpret_cast<float2*>(&out[(size_t)m * N + col0]) =
                        make_float2(v0, v1);
                }
            }
        }
    }
}

// ---------------------------------------------------------------------------
// Tensor-core flash attention.
// CTA: 128 queries x dk=64; loop over 64-key tiles; 8 warps x 16 query rows.
// S = Q@K^T (m16n8k8 tf32), online softmax in fragments, P staged via smem,
// O += P@V (m16n8k8 tf32). LDA2=72 -> conflict-free fragment LDS.64.
// ---------------------------------------------------------------------------
#define LDA2 72

__global__ void __launch_bounds__(256)
attn_mma(const float* __restrict__ aw,
         const float* __restrict__ vv,
         float* __restrict__ x)
{
    extern __shared__ uint32_t smu[];
    uint32_t* Qs = smu;                 // [128][72]
    uint32_t* Ks = Qs + 128 * LDA2;     // [64][72]   [key][csw(d)]
    uint32_t* Vs = Ks + 64 * LDA2;      // [64][72]   [d][csw(key)]
    uint32_t* Ps = Vs + 64 * LDA2;      // [128][72]  [qrow][csw(key)]

    const int tid  = threadIdx.x;
    const int wid  = tid >> 5;
    const int lane = tid & 31;
    const int lrow = lane >> 2;
    const int lcol = lane & 3;
    const int bh   = blockIdx.y;
    const int q0   = blockIdx.x * 128;

    const float* Abh = aw + (size_t)bh * NS * NDK;
    const float* Vbh = vv + (size_t)bh * NS * NDK;

    // Load Q tile: 128 rows x 64 d (tf32, paired layout)
    for (int i = tid; i < 128 * 16; i += 256) {
        const int r = i >> 4, c4 = (i & 15) * 4;
        const float4 v = *reinterpret_cast<const float4*>(
            &Abh[(size_t)(q0 + r) * NDK + c4]);
        const float v4[4] = {v.x, v.y, v.z, v.w};
#pragma unroll
        for (int e = 0; e < 4; e++)
            Qs[r * LDA2 + csw(c4 + e)] = f2tf32(v4[e]);
    }

    float m_[2], l_[2], o[8][4];
    m_[0] = m_[1] = -CUDART_INF_F;
    l_[0] = l_[1] = 0.f;
#pragma unroll
    for (int nf = 0; nf < 8; nf++)
#pragma unroll
        for (int r = 0; r < 4; r++) o[nf][r] = 0.f;

    const int mrow = wid * 16 + lrow;   // this thread's base query row (and +8)

    for (int k0 = 0; k0 < NS; k0 += 64) {
        // K tile: [key][csw(d)]
        for (int i = tid; i < 64 * 16; i += 256) {
            const int r = i >> 4, c4 = (i & 15) * 4;
            const float4 v = *reinterpret_cast<const float4*>(
                &Abh[(size_t)(k0 + r) * NDK + c4]);
            const float v4[4] = {v.x, v.y, v.z, v.w};
#pragma unroll
            for (int e = 0; e < 4; e++)
                Ks[r * LDA2 + csw(c4 + e)] = f2tf32(v4[e]);
        }
        // V tile transposed: [d][csw(key)]; lane-major over key -> bank-perm stores
        for (int i = tid; i < 64 * 16; i += 256) {
            const int c = i & 63, d4 = (i >> 6) << 2;
            const float4 v = *reinterpret_cast<const float4*>(
                &Vbh[(size_t)(k0 + c) * NDK + d4]);
            const int cc = csw(c);
            const float v4[4] = {v.x, v.y, v.z, v.w};
#pragma unroll
            for (int e = 0; e < 4; e++)
                Vs[(d4 + e) * LDA2 + cc] = f2tf32(v4[e]);
        }
        __syncthreads();

        // --- S = Q @ K^T  (warp: 16 x 64) ---
        float s[8][4];
#pragma unroll
        for (int nf = 0; nf < 8; nf++)
#pragma unroll
            for (int r = 0; r < 4; r++) s[nf][r] = 0.f;

#pragma unroll
        for (int kb = 0; kb < 64; kb += 8) {
            const uint2 p0 = *reinterpret_cast<const uint2*>(
                &Qs[mrow * LDA2 + kb + 2 * lcol]);
            const uint2 p1 = *reinterpret_cast<const uint2*>(
                &Qs[(mrow + 8) * LDA2 + kb + 2 * lcol]);
#pragma unroll
            for (int nf = 0; nf < 8; nf++) {
                const uint2 q = *reinterpret_cast<const uint2*>(
                    &Ks[(nf * 8 + lrow) * LDA2 + kb + 2 * lcol]);
                mma8(s[nf], p0.x, p1.x, p0.y, p1.y, q.x, q.y);
            }
        }

        // --- online softmax (rows mrow, mrow+8) ---
#pragma unroll
        for (int hh = 0; hh < 2; hh++) {
            float rm = -CUDART_INF_F;
#pragma unroll
            for (int nf = 0; nf < 8; nf++) {
                s[nf][2 * hh + 0] *= 0.125f;
                s[nf][2 * hh + 1] *= 0.125f;
                rm = fmaxf(rm, fmaxf(s[nf][2 * hh + 0], s[nf][2 * hh + 1]));
            }
            rm = fmaxf(rm, __shfl_xor_sync(0xffffffffu, rm, 1));
            rm = fmaxf(rm, __shfl_xor_sync(0xffffffffu, rm, 2));

            const float mnew  = fmaxf(m_[hh], rm);
            const float alpha = __expf(m_[hh] - mnew);
            float ps = 0.f;
#pragma unroll
            for (int nf = 0; nf < 8; nf++) {
                s[nf][2 * hh + 0] = __expf(s[nf][2 * hh + 0] - mnew);
                s[nf][2 * hh + 1] = __expf(s[nf][2 * hh + 1] - mnew);
                ps += s[nf][2 * hh + 0] + s[nf][2 * hh + 1];
            }
            ps += __shfl_xor_sync(0xffffffffu, ps, 1);
            ps += __shfl_xor_sync(0xffffffffu, ps, 2);

            l_[hh] = l_[hh] * alpha + ps;
            m_[hh] = mnew;
#pragma unroll
            for (int nf = 0; nf < 8; nf++) {
                o[nf][2 * hh + 0] *= alpha;
                o[nf][2 * hh + 1] *= alpha;
            }
        }

        // --- stage P (tf32) ---
#pragma unroll
        for (int nf = 0; nf < 8; nf++) {
            const int c0 = nf * 8 + 2 * lcol;
            Ps[mrow * LDA2 + csw(c0)]           = f2tf32(s[nf][0]);
            Ps[mrow * LDA2 + csw(c0 + 1)]       = f2tf32(s[nf][1]);
            Ps[(mrow + 8) * LDA2 + csw(c0)]     = f2tf32(s[nf][2]);
            Ps[(mrow + 8) * LDA2 + csw(c0 + 1)] = f2tf32(s[nf][3]);
        }
        __syncwarp();

        // --- O += P @ V  (warp: 16 x 64, k = 64 keys) ---
#pragma unroll
        for (int kb = 0; kb < 64; kb += 8) {
            const uint2 p0 = *reinterpret_cast<const uint2*>(
                &Ps[mrow * LDA2 + kb + 2 * lcol]);
            const uint2 p1 = *reinterpret_cast<const uint2*>(
                &Ps[(mrow + 8) * LDA2 + kb + 2 * lcol]);
#pragma unroll
            for (int nf = 0; nf < 8; nf++) {
                const uint2 q = *reinterpret_cast<const uint2*>(
                    &Vs[(nf * 8 + lrow) * LDA2 + kb + 2 * lcol]);
                mma8(o[nf], p0.x, p1.x, p0.y, p1.y, q.x, q.y);
            }
        }
        __syncthreads();
    }

    // Epilogue: x[b, s, h*64+d] = o / l
    const int b = bh >> 3, h = bh & 7;
#pragma unroll
    for (int hh = 0; hh < 2; hh++) {
        const int r = q0 + mrow + hh * 8;
        const float inv = 1.f / l_[hh];
#pragma unroll
        for (int nf = 0; nf < 8; nf++) {
            const int d = nf * 8 + 2 * lcol;
            *reinterpret_cast<float2*>(
                &x[((size_t)(b * NS + r)) * NF + h * NDK + d]) =
                make_float2(o[nf][2 * hh + 0] * inv, o[nf][2 * hh + 1] * inv);
        }
    }
}

// ---------------------------------------------------------------------------
extern "C" void kernel_launch(void* const* d_in, const int* in_sizes, int n_in,
                              void* d_out, int out_size)
{
    const float* query = (const float*)d_in[0];
    // d_in[1] = key_t (unused by the synthesizer module)
    const float* value = (const float*)d_in[2];
    const float* w1 = (const float*)d_in[3];
    const float* b1 = (const float*)d_in[4];
    const float* w2 = (const float*)d_in[5];
    const float* b2 = (const float*)d_in[6];
    const float* wv = (const float*)d_in[7];
    const float* bv = (const float*)d_in[8];
    const float* wo = (const float*)d_in[9];
    const float* bo = (const float*)d_in[10];
    float* out = (float*)d_out;

    float *ph, *paw, *pv, *px;
    cudaGetSymbolAddress((void**)&ph,  g_h);
    cudaGetSymbolAddress((void**)&paw, g_aw);
    cudaGetSymbolAddress((void**)&pv,  g_v);
    cudaGetSymbolAddress((void**)&px,  g_x);

    const dim3 blk(256);
    const int attn_smem = (128 + 64 + 64 + 128) * LDA2 * 4;   // 110,592 B
    cudaFuncSetAttribute(attn_mma, cudaFuncAttributeMaxDynamicSharedMemorySize,
                         attn_smem);

    // 1) h = relu(q @ w1 + b1)          [8192,1024]
    mma_gemm<0><<<dim3(NHID / 128, NM / 128), blk>>>(NM, NHID, NF, query, w1, b1, ph);
    // 2) aw = h @ w2 + b2 -> [B,H,S,dk]
    mma_gemm<1><<<dim3(NF / 128, NM / 128), blk>>>(NM, NF, NHID, ph, w2, b2, paw);
    // 3) v = value @ wv + bv -> [B,H,S,dk]
    mma_gemm<1><<<dim3(NF / 128, NM / 128), blk>>>(NM, NF, NF, value, wv, bv, pv);
    // 4) tensor-core flash attention -> x [B,S,F]
    attn_mma<<<dim3(NS / 128, NB * NH), blk, attn_smem>>>(paw, pv, px);
    // 5) out = x @ wo + bo
    mma_gemm<2><<<dim3(NF / 128, NM / 128), blk>>>(NM, NF, NF, px, wo, bo, out);
}

// round 7
// speedup vs baseline: 2.2562x; 1.1103x over previous
#include <cuda_runtime.h>
#include <cuda_bf16.h>
#include <math_constants.h>
#include <cstdint>

// Problem constants
#define NB    8
#define NS    1024
#define NF    512
#define NHID  1024
#define NH    8
#define NDK   64
#define NM    (NB * NS)        // 8192 token rows

// Scratch (allocation-free: __device__ globals)
__device__ float g_h [NM * NHID];            // 32 MB  relu(q@w1+b1)
__device__ float g_aw[NB * NH * NS * NDK];   // 16 MB  [B,H,S,dk]
__device__ float g_v [NB * NH * NS * NDK];   // 16 MB  [B,H,S,dk]
__device__ float g_x [NM * NF];              // 16 MB  [B,S,F]

__device__ __forceinline__ uint32_t f2tf32(float f) {
    uint32_t u;
    asm("cvt.rna.tf32.f32 %0, %1;" : "=r"(u) : "f"(f));
    return u;
}

// smem column pairing: (k, k+4) adjacent so an A/B fragment pair is one LDS.64
__device__ __forceinline__ int csw(int k) {
    return (k & ~7) + 2 * (k & 3) + ((k >> 2) & 1);
}

__device__ __forceinline__ void mma8(float* c,
                                     uint32_t a0, uint32_t a1, uint32_t a2, uint32_t a3,
                                     uint32_t b0, uint32_t b1) {
    asm volatile(
        "mma.sync.aligned.m16n8k8.row.col.f32.tf32.tf32.f32 "
        "{%0,%1,%2,%3}, {%4,%5,%6,%7}, {%8,%9}, {%0,%1,%2,%3};"
        : "+f"(c[0]), "+f"(c[1]), "+f"(c[2]), "+f"(c[3])
        : "r"(a0), "r"(a1), "r"(a2), "r"(a3), "r"(b0), "r"(b1));
}

// ---------------------------------------------------------------------------
// TF32 tensor-core GEMM, double-buffered + register prefetch.
// CTA tile 128x128, BK=32, 256 threads = 8 warps (2x4), warp tile 64x32.
// LDA=40 (== 8 mod 32) -> conflict-free fragment LDS.64.
// Dynamic smem: 2 bufs x (A 128x40 + B 128x40) u32 = 81,920 B.
// ---------------------------------------------------------------------------
#define GLDA 40

template <int MODE>
__global__ void __launch_bounds__(256)
mma_gemm(int M, int N, int K,
         const float* __restrict__ A,
         const float* __restrict__ W,
         const float* __restrict__ bias,
         float* __restrict__ out)
{
    extern __shared__ uint32_t sg[];
    uint32_t (*As2)[GLDA] = reinterpret_cast<uint32_t(*)[GLDA]>(sg);            // [2*128][40]
    uint32_t (*Bs2)[GLDA] = reinterpret_cast<uint32_t(*)[GLDA]>(sg + 2 * 128 * GLDA);

    const int tid  = threadIdx.x;
    const int bm   = blockIdx.y * 128;
    const int bn   = blockIdx.x * 128;
    const int wid  = tid >> 5;
    const int lane = tid & 31;
    const int wr   = wid & 1;
    const int wc   = wid >> 1;
    const int lrow = lane >> 2;
    const int lcol = lane & 3;

    // Loader mappings (2 units per thread):
    //  A unit u: row = u>>2 (0..127), kh = u&3 -> k in [kh*8, kh*8+8)
    //  B unit u: n4 = u&31, kk = u>>5 (0..15) -> k = (kk>>2)*8 + (kk&3), rows n4*4..+3
    float4 pa[2][2], pb[2][2];

    auto load_tiles = [&](int k0) {
#pragma unroll
        for (int i = 0; i < 2; i++) {
            const int u = tid + i * 256;
            const int row = u >> 2, kh = u & 3;
            const float* p = &A[(size_t)(bm + row) * K + k0 + kh * 8];
            pa[i][0] = *reinterpret_cast<const float4*>(p);
            pa[i][1] = *reinterpret_cast<const float4*>(p + 4);
            const int n4 = u & 31, kk = u >> 5;
            const int kb = ((kk >> 2) * 8) + (kk & 3);
            const float* q = &W[(size_t)(k0 + kb) * N + bn + n4 * 4];
            pb[i][0] = *reinterpret_cast<const float4*>(q);
            pb[i][1] = *reinterpret_cast<const float4*>(q + (size_t)4 * N);
        }
    };
    auto store_tiles = [&](int buf) {
#pragma unroll
        for (int i = 0; i < 2; i++) {
            const int u = tid + i * 256;
            const int row = u >> 2, kh = u & 3;
            uint32_t* da = &As2[buf * 128 + row][kh * 8];
            // pairs (k, k+4) -> uint2 at cols kh*8 + {0,2,4,6}
            *reinterpret_cast<uint2*>(da + 0) =
                make_uint2(f2tf32(pa[i][0].x), f2tf32(pa[i][1].x));
            *reinterpret_cast<uint2*>(da + 2) =
                make_uint2(f2tf32(pa[i][0].y), f2tf32(pa[i][1].y));
            *reinterpret_cast<uint2*>(da + 4) =
                make_uint2(f2tf32(pa[i][0].z), f2tf32(pa[i][1].z));
            *reinterpret_cast<uint2*>(da + 6) =
                make_uint2(f2tf32(pa[i][0].w), f2tf32(pa[i][1].w));
            const int n4 = u & 31, kk = u >> 5;
            const int colb = ((kk >> 2) * 8) + 2 * (kk & 3);
            const float bv0[4] = {pb[i][0].x, pb[i][0].y, pb[i][0].z, pb[i][0].w};
            const float bv1[4] = {pb[i][1].x, pb[i][1].y, pb[i][1].z, pb[i][1].w};
#pragma unroll
            for (int e = 0; e < 4; e++)
                *reinterpret_cast<uint2*>(&Bs2[buf * 128 + n4 * 4 + e][colb]) =
                    make_uint2(f2tf32(bv0[e]), f2tf32(bv1[e]));
        }
    };

    float c[4][4][4];
#pragma unroll
    for (int mf = 0; mf < 4; mf++)
#pragma unroll
        for (int nf = 0; nf < 4; nf++)
#pragma unroll
            for (int r = 0; r < 4; r++) c[mf][nf][r] = 0.f;

    const int T = K >> 5;   // K/32, >= 16 here
    load_tiles(0);
    store_tiles(0);
    load_tiles(32);
    __syncthreads();

    int cur = 0;
    for (int t = 0; t < T; t++) {
        if (t + 1 < T) {
            store_tiles(cur ^ 1);
            if (t + 2 < T) load_tiles((t + 2) << 5);
        }
#pragma unroll
        for (int kb = 0; kb < 32; kb += 8) {
            uint32_t af[4][4];
#pragma unroll
            for (int mf = 0; mf < 4; mf++) {
                const int m = cur * 128 + wr * 64 + mf * 16 + lrow;
                const uint2 p0 = *reinterpret_cast<const uint2*>(&As2[m][kb + 2 * lcol]);
                const uint2 p1 = *reinterpret_cast<const uint2*>(&As2[m + 8][kb + 2 * lcol]);
                af[mf][0] = p0.x; af[mf][2] = p0.y;
                af[mf][1] = p1.x; af[mf][3] = p1.y;
            }
            uint32_t bf[4][2];
#pragma unroll
            for (int nf = 0; nf < 4; nf++) {
                const int n = cur * 128 + wc * 32 + nf * 8 + lrow;
                const uint2 q = *reinterpret_cast<const uint2*>(&Bs2[n][kb + 2 * lcol]);
                bf[nf][0] = q.x; bf[nf][1] = q.y;
            }
#pragma unroll
            for (int mf = 0; mf < 4; mf++)
#pragma unroll
                for (int nf = 0; nf < 4; nf++)
                    mma8(c[mf][nf], af[mf][0], af[mf][1], af[mf][2], af[mf][3],
                         bf[nf][0], bf[nf][1]);
        }
        __syncthreads();
        cur ^= 1;
    }

#pragma unroll
    for (int mf = 0; mf < 4; mf++) {
#pragma unroll
        for (int nf = 0; nf < 4; nf++) {
            const int row0 = bm + wr * 64 + mf * 16 + lrow;
            const int col0 = bn + wc * 32 + nf * 8 + 2 * lcol;
            const float bsum0 = bias[col0], bsum1 = bias[col0 + 1];
#pragma unroll
            for (int half = 0; half < 2; half++) {
                const int m = row0 + half * 8;
                float v0 = c[mf][nf][half * 2 + 0] + bsum0;
                float v1 = c[mf][nf][half * 2 + 1] + bsum1;
                if (MODE == 0) { v0 = fmaxf(v0, 0.f); v1 = fmaxf(v1, 0.f); }
                if (MODE == 1) {
                    const int b = m >> 10, s = m & 1023;
                    const int h = col0 >> 6, d = col0 & 63;
                    *reinterpret_cast<float2*>(
                        &out[((((size_t)b * NH + h) * NS + s) * NDK) + d]) =
                        make_float2(v0, v1);
                } else {
                    *reinterpret_cast<float2*>(&out[(size_t)m * N + col0]) =
                        make_float2(v0, v1);
                }
            }
        }
    }
}

// ---------------------------------------------------------------------------
// Tensor-core flash attention (unchanged from passing round-6 kernel)
// ---------------------------------------------------------------------------
#define LDA2 72

__global__ void __launch_bounds__(256)
attn_mma(const float* __restrict__ aw,
         const float* __restrict__ vv,
         float* __restrict__ x)
{
    extern __shared__ uint32_t smu[];
    uint32_t* Qs = smu;                 // [128][72]
    uint32_t* Ks = Qs + 128 * LDA2;     // [64][72]   [key][csw(d)]
    uint32_t* Vs = Ks + 64 * LDA2;      // [64][72]   [d][csw(key)]
    uint32_t* Ps = Vs + 64 * LDA2;      // [128][72]  [qrow][csw(key)]

    const int tid  = threadIdx.x;
    const int wid  = tid >> 5;
    const int lane = tid & 31;
    const int lrow = lane >> 2;
    const int lcol = lane & 3;
    const int bh   = blockIdx.y;
    const int q0   = blockIdx.x * 128;

    const float* Abh = aw + (size_t)bh * NS * NDK;
    const float* Vbh = vv + (size_t)bh * NS * NDK;

    for (int i = tid; i < 128 * 16; i += 256) {
        const int r = i >> 4, c4 = (i & 15) * 4;
        const float4 v = *reinterpret_cast<const float4*>(
            &Abh[(size_t)(q0 + r) * NDK + c4]);
        const float v4[4] = {v.x, v.y, v.z, v.w};
#pragma unroll
        for (int e = 0; e < 4; e++)
            Qs[r * LDA2 + csw(c4 + e)] = f2tf32(v4[e]);
    }

    float m_[2], l_[2], o[8][4];
    m_[0] = m_[1] = -CUDART_INF_F;
    l_[0] = l_[1] = 0.f;
#pragma unroll
    for (int nf = 0; nf < 8; nf++)
#pragma unroll
        for (int r = 0; r < 4; r++) o[nf][r] = 0.f;

    const int mrow = wid * 16 + lrow;

    for (int k0 = 0; k0 < NS; k0 += 64) {
        for (int i = tid; i < 64 * 16; i += 256) {
            const int r = i >> 4, c4 = (i & 15) * 4;
            const float4 v = *reinterpret_cast<const float4*>(
                &Abh[(size_t)(k0 + r) * NDK + c4]);
            const float v4[4] = {v.x, v.y, v.z, v.w};
#pragma unroll
            for (int e = 0; e < 4; e++)
                Ks[r * LDA2 + csw(c4 + e)] = f2tf32(v4[e]);
        }
        for (int i = tid; i < 64 * 16; i += 256) {
            const int c = i & 63, d4 = (i >> 6) << 2;
            const float4 v = *reinterpret_cast<const float4*>(
                &Vbh[(size_t)(k0 + c) * NDK + d4]);
            const int cc = csw(c);
            const float v4[4] = {v.x, v.y, v.z, v.w};
#pragma unroll
            for (int e = 0; e < 4; e++)
                Vs[(d4 + e) * LDA2 + cc] = f2tf32(v4[e]);
        }
        __syncthreads();

        float s[8][4];
#pragma unroll
        for (int nf = 0; nf < 8; nf++)
#pragma unroll
            for (int r = 0; r < 4; r++) s[nf][r] = 0.f;

#pragma unroll
        for (int kb = 0; kb < 64; kb += 8) {
            const uint2 p0 = *reinterpret_cast<const uint2*>(
                &Qs[mrow * LDA2 + kb + 2 * lcol]);
            const uint2 p1 = *reinterpret_cast<const uint2*>(
                &Qs[(mrow + 8) * LDA2 + kb + 2 * lcol]);
#pragma unroll
            for (int nf = 0; nf < 8; nf++) {
                const uint2 q = *reinterpret_cast<const uint2*>(
                    &Ks[(nf * 8 + lrow) * LDA2 + kb + 2 * lcol]);
                mma8(s[nf], p0.x, p1.x, p0.y, p1.y, q.x, q.y);
            }
        }

#pragma unroll
        for (int hh = 0; hh < 2; hh++) {
            float rm = -CUDART_INF_F;
#pragma unroll
            for (int nf = 0; nf < 8; nf++) {
                s[nf][2 * hh + 0] *= 0.125f;
                s[nf][2 * hh + 1] *= 0.125f;
                rm = fmaxf(rm, fmaxf(s[nf][2 * hh + 0], s[nf][2 * hh + 1]));
            }
            rm = fmaxf(rm, __shfl_xor_sync(0xffffffffu, rm, 1));
            rm = fmaxf(rm, __shfl_xor_sync(0xffffffffu, rm, 2));

            const float mnew  = fmaxf(m_[hh], rm);
            const float alpha = __expf(m_[hh] - mnew);
            float ps = 0.f;
#pragma unroll
            for (int nf = 0; nf < 8; nf++) {
                s[nf][2 * hh + 0] = __expf(s[nf][2 * hh + 0] - mnew);
                s[nf][2 * hh + 1] = __expf(s[nf][2 * hh + 1] - mnew);
                ps += s[nf][2 * hh + 0] + s[nf][2 * hh + 1];
            }
            ps += __shfl_xor_sync(0xffffffffu, ps, 1);
            ps += __shfl_xor_sync(0xffffffffu, ps, 2);

            l_[hh] = l_[hh] * alpha + ps;
            m_[hh] = mnew;
#pragma unroll
            for (int nf = 0; nf < 8; nf++) {
                o[nf][2 * hh + 0] *= alpha;
                o[nf][2 * hh + 1] *= alpha;
            }
        }

#pragma unroll
        for (int nf = 0; nf < 8; nf++) {
            const int c0 = nf * 8 + 2 * lcol;
            Ps[mrow * LDA2 + csw(c0)]           = f2tf32(s[nf][0]);
            Ps[mrow * LDA2 + csw(c0 + 1)]       = f2tf32(s[nf][1]);
            Ps[(mrow + 8) * LDA2 + csw(c0)]     = f2tf32(s[nf][2]);
            Ps[(mrow + 8) * LDA2 + csw(c0 + 1)] = f2tf32(s[nf][3]);
        }
        __syncwarp();

#pragma unroll
        for (int kb = 0; kb < 64; kb += 8) {
            const uint2 p0 = *reinterpret_cast<const uint2*>(
                &Ps[mrow * LDA2 + kb + 2 * lcol]);
            const uint2 p1 = *reinterpret_cast<const uint2*>(
                &Ps[(mrow + 8) * LDA2 + kb + 2 * lcol]);
#pragma unroll
            for (int nf = 0; nf < 8; nf++) {
                const uint2 q = *reinterpret_cast<const uint2*>(
                    &Vs[(nf * 8 + lrow) * LDA2 + kb + 2 * lcol]);
                mma8(o[nf], p0.x, p1.x, p0.y, p1.y, q.x, q.y);
            }
        }
        __syncthreads();
    }

    const int b = bh >> 3, h = bh & 7;
#pragma unroll
    for (int hh = 0; hh < 2; hh++) {
        const int r = q0 + mrow + hh * 8;
        const float inv = 1.f / l_[hh];
#pragma unroll
        for (int nf = 0; nf < 8; nf++) {
            const int d = nf * 8 + 2 * lcol;
            *reinterpret_cast<float2*>(
                &x[((size_t)(b * NS + r)) * NF + h * NDK + d]) =
                make_float2(o[nf][2 * hh + 0] * inv, o[nf][2 * hh + 1] * inv);
        }
    }
}

// ---------------------------------------------------------------------------
extern "C" void kernel_launch(void* const* d_in, const int* in_sizes, int n_in,
                              void* d_out, int out_size)
{
    const float* query = (const float*)d_in[0];
    // d_in[1] = key_t (unused by the synthesizer module)
    const float* value = (const float*)d_in[2];
    const float* w1 = (const float*)d_in[3];
    const float* b1 = (const float*)d_in[4];
    const float* w2 = (const float*)d_in[5];
    const float* b2 = (const float*)d_in[6];
    const float* wv = (const float*)d_in[7];
    const float* bv = (const float*)d_in[8];
    const float* wo = (const float*)d_in[9];
    const float* bo = (const float*)d_in[10];
    float* out = (float*)d_out;

    float *ph, *paw, *pv, *px;
    cudaGetSymbolAddress((void**)&ph,  g_h);
    cudaGetSymbolAddress((void**)&paw, g_aw);
    cudaGetSymbolAddress((void**)&pv,  g_v);
    cudaGetSymbolAddress((void**)&px,  g_x);

    const dim3 blk(256);
    const int gemm_smem = 2 * 2 * 128 * GLDA * 4;             // 81,920 B
    const int attn_smem = (128 + 64 + 64 + 128) * LDA2 * 4;   // 110,592 B
    cudaFuncSetAttribute(mma_gemm<0>, cudaFuncAttributeMaxDynamicSharedMemorySize, gemm_smem);
    cudaFuncSetAttribute(mma_gemm<1>, cudaFuncAttributeMaxDynamicSharedMemorySize, gemm_smem);
    cudaFuncSetAttribute(mma_gemm<2>, cudaFuncAttributeMaxDynamicSharedMemorySize, gemm_smem);
    cudaFuncSetAttribute(attn_mma, cudaFuncAttributeMaxDynamicSharedMemorySize, attn_smem);

    // 1) h = relu(q @ w1 + b1)          [8192,1024]
    mma_gemm<0><<<dim3(NHID / 128, NM / 128), blk, gemm_smem>>>(NM, NHID, NF, query, w1, b1, ph);
    // 2) aw = h @ w2 + b2 -> [B,H,S,dk]
    mma_gemm<1><<<dim3(NF / 128, NM / 128), blk, gemm_smem>>>(NM, NF, NHID, ph, w2, b2, paw);
    // 3) v = value @ wv + bv -> [B,H,S,dk]
    mma_gemm<1><<<dim3(NF / 128, NM / 128), blk, gemm_smem>>>(NM, NF, NF, value, wv, bv, pv);
    // 4) tensor-core flash attention -> x [B,S,F]
    attn_mma<<<dim3(NS / 128, NB * NH), blk, attn_smem>>>(paw, pv, px);
    // 5) out = x @ wo + bo
    mma_gemm<2><<<dim3(NF / 128, NM / 128), blk, gemm_smem>>>(NM, NF, NF, px, wo, bo, out);
}

// round 8
// speedup vs baseline: 4.3794x; 1.9411x over previous
#include <cuda_runtime.h>
#include <cuda_fp16.h>
#include <math_constants.h>
#include <cstdint>

// Problem constants
#define NB    8
#define NS    1024
#define NF    512
#define NHID  1024
#define NH    8
#define NDK   64
#define NM    (NB * NS)        // 8192 token rows

// Scratch (allocation-free: __device__ globals)
__device__ float g_h [NM * NHID];            // 32 MB  relu(q@w1+b1)
__device__ float g_aw[NB * NH * NS * NDK];   // 16 MB  [B,H,S,dk]
__device__ float g_v [NB * NH * NS * NDK];   // 16 MB  [B,H,S,dk]
__device__ float g_x [NM * NF];              // 16 MB  [B,S,F]

__device__ __forceinline__ uint32_t h2pack(float a, float b) {
    __half2 h = __floats2half2_rn(a, b);
    return reinterpret_cast<uint32_t&>(h);
}
__device__ __forceinline__ float f4e(const float4& v, int e) {
    return e == 0 ? v.x : e == 1 ? v.y : e == 2 ? v.z : v.w;
}
// pairing: half-pair p and p+4 adjacent (one uint2 = one A/B fragment half)
__device__ __forceinline__ int csw(int p) {
    return (p & ~7) + 2 * (p & 3) + ((p >> 2) & 1);
}

__device__ __forceinline__ void mma16(float* c,
                                      uint32_t a0, uint32_t a1, uint32_t a2, uint32_t a3,
                                      uint32_t b0, uint32_t b1) {
    asm volatile(
        "mma.sync.aligned.m16n8k16.row.col.f32.f16.f16.f32 "
        "{%0,%1,%2,%3}, {%4,%5,%6,%7}, {%8,%9}, {%0,%1,%2,%3};"
        : "+f"(c[0]), "+f"(c[1]), "+f"(c[2]), "+f"(c[3])
        : "r"(a0), "r"(a1), "r"(a2), "r"(a3), "r"(b0), "r"(b1));
}

// ---------------------------------------------------------------------------
// FP16 tensor-core GEMM, double-buffered + register prefetch.
// CTA tile 128x128, BK=32, 256 threads = 8 warps (2x4), warp tile 64x32.
// Smem unit = half2. LDA=24 u32 (conflict-free fragment LDS.64).
// B rows get XOR swizzle col ^= 2*((n>>2)&7) to fix store bank conflicts.
// Dynamic smem: 2 bufs x (A 128x24 + B 128x24) u32 = 49,152 B.
// ---------------------------------------------------------------------------
#define GLDAH 24

template <int MODE>
__global__ void __launch_bounds__(256)
hgemm(int M, int N, int K,
      const float* __restrict__ A,
      const float* __restrict__ W,
      const float* __restrict__ bias,
      float* __restrict__ out)
{
    extern __shared__ uint32_t sg[];
    uint32_t (*As2)[GLDAH] = reinterpret_cast<uint32_t(*)[GLDAH]>(sg);
    uint32_t (*Bs2)[GLDAH] = reinterpret_cast<uint32_t(*)[GLDAH]>(sg + 2 * 128 * GLDAH);

    const int tid  = threadIdx.x;
    const int bm   = blockIdx.y * 128;
    const int bn   = blockIdx.x * 128;
    const int wid  = tid >> 5;
    const int lane = tid & 31;
    const int wr   = wid & 1;
    const int wc   = wid >> 1;
    const int lrow = lane >> 2;
    const int lcol = lane & 3;

    // A loader: 2 units (rows r, r+64), k offset a_k, smem col a_c
    const int a_r  = tid >> 2;                 // 0..63
    const int a_rt = tid & 3;
    const int a_k  = 16 * (a_rt >> 1) + 4 * (a_rt & 1);   // {0,4,16,20}
    const int a_c  = 8 * (a_rt >> 1) + 4 * (a_rt & 1);    // {0,4,8,12}
    // B loader: 1 unit: 4 n-values x (k,k+1,k+8,k+9)
    const int b_n4 = tid & 31;
    const int b_rt = tid >> 5;
    const int b_k  = 16 * (b_rt >> 2) + 2 * (b_rt & 3);   // k row base
    const int b_c  = (8 * (b_rt >> 2) + 2 * (b_rt & 3)) ^ (2 * (b_n4 & 7));  // XOR store col

    float4 pa[2][2], pb[4];

    auto load_tiles = [&](int k0) {
        const float* p0 = &A[(size_t)(bm + a_r) * K + k0 + a_k];
        pa[0][0] = *reinterpret_cast<const float4*>(p0);
        pa[0][1] = *reinterpret_cast<const float4*>(p0 + 8);
        const float* p1 = &A[(size_t)(bm + a_r + 64) * K + k0 + a_k];
        pa[1][0] = *reinterpret_cast<const float4*>(p1);
        pa[1][1] = *reinterpret_cast<const float4*>(p1 + 8);
        const float* q = &W[(size_t)(k0 + b_k) * N + bn + 4 * b_n4];
        pb[0] = *reinterpret_cast<const float4*>(q);
        pb[1] = *reinterpret_cast<const float4*>(q + N);
        pb[2] = *reinterpret_cast<const float4*>(q + (size_t)8 * N);
        pb[3] = *reinterpret_cast<const float4*>(q + (size_t)9 * N);
    };
    auto store_tiles = [&](int buf) {
#pragma unroll
        for (int i = 0; i < 2; i++) {
            uint32_t* da = &As2[buf * 128 + a_r + i * 64][a_c];
            *reinterpret_cast<uint2*>(da + 0) =
                make_uint2(h2pack(pa[i][0].x, pa[i][0].y), h2pack(pa[i][1].x, pa[i][1].y));
            *reinterpret_cast<uint2*>(da + 2) =
                make_uint2(h2pack(pa[i][0].z, pa[i][0].w), h2pack(pa[i][1].z, pa[i][1].w));
        }
#pragma unroll
        for (int e = 0; e < 4; e++)
            *reinterpret_cast<uint2*>(&Bs2[buf * 128 + 4 * b_n4 + e][b_c]) =
                make_uint2(h2pack(f4e(pb[0], e), f4e(pb[1], e)),
                           h2pack(f4e(pb[2], e), f4e(pb[3], e)));
    };

    float c[4][4][4];
#pragma unroll
    for (int mf = 0; mf < 4; mf++)
#pragma unroll
        for (int nf = 0; nf < 4; nf++)
#pragma unroll
            for (int r = 0; r < 4; r++) c[mf][nf][r] = 0.f;

    const int T = K >> 5;
    load_tiles(0);
    store_tiles(0);
    load_tiles(32);
    __syncthreads();

    int cur = 0;
    for (int t = 0; t < T; t++) {
        if (t + 1 < T) {
            store_tiles(cur ^ 1);
            if (t + 2 < T) load_tiles((t + 2) << 5);
        }
#pragma unroll
        for (int kb = 0; kb < 2; kb++) {
            const int col = 8 * kb + 2 * lcol;
            uint32_t af[4][4];
#pragma unroll
            for (int mf = 0; mf < 4; mf++) {
                const int m = cur * 128 + wr * 64 + mf * 16 + lrow;
                const uint2 p0 = *reinterpret_cast<const uint2*>(&As2[m][col]);
                const uint2 p1 = *reinterpret_cast<const uint2*>(&As2[m + 8][col]);
                af[mf][0] = p0.x; af[mf][2] = p0.y;
                af[mf][1] = p1.x; af[mf][3] = p1.y;
            }
            uint32_t bf[4][2];
#pragma unroll
            for (int nf = 0; nf < 4; nf++) {
                const int nl = wc * 32 + nf * 8 + lrow;
                const int cb = col ^ (2 * ((nl >> 2) & 7));
                const uint2 q = *reinterpret_cast<const uint2*>(&Bs2[cur * 128 + nl][cb]);
                bf[nf][0] = q.x; bf[nf][1] = q.y;
            }
#pragma unroll
            for (int mf = 0; mf < 4; mf++)
#pragma unroll
                for (int nf = 0; nf < 4; nf++)
                    mma16(c[mf][nf], af[mf][0], af[mf][1], af[mf][2], af[mf][3],
                          bf[nf][0], bf[nf][1]);
        }
        __syncthreads();
        cur ^= 1;
    }

#pragma unroll
    for (int mf = 0; mf < 4; mf++) {
#pragma unroll
        for (int nf = 0; nf < 4; nf++) {
            const int row0 = bm + wr * 64 + mf * 16 + lrow;
            const int col0 = bn + wc * 32 + nf * 8 + 2 * lcol;
            const float bsum0 = bias[col0], bsum1 = bias[col0 + 1];
#pragma unroll
            for (int half = 0; half < 2; half++) {
                const int m = row0 + half * 8;
                float v0 = c[mf][nf][half * 2 + 0] + bsum0;
                float v1 = c[mf][nf][half * 2 + 1] + bsum1;
                if (MODE == 0) { v0 = fmaxf(v0, 0.f); v1 = fmaxf(v1, 0.f); }
                if (MODE == 1) {
                    const int b = m >> 10, s = m & 1023;
                    const int h = col0 >> 6, d = col0 & 63;
                    *reinterpret_cast<float2*>(
                        &out[((((size_t)b * NH + h) * NS + s) * NDK) + d]) =
                        make_float2(v0, v1);
                } else {
                    *reinterpret_cast<float2*>(&out[(size_t)m * N + col0]) =
                        make_float2(v0, v1);
                }
            }
        }
    }
}

// ---------------------------------------------------------------------------
// FP16 tensor-core flash attention.
// CTA: 128 queries x dk=64; 64-key tiles; 8 warps x 16 query rows.
// Smem 61,440 B -> 2 CTAs/SM. m16n8k16 halves mma count vs tf32.
// ---------------------------------------------------------------------------
#define ALDA 40

__global__ void __launch_bounds__(256)
attn_hmma(const float* __restrict__ aw,
          const float* __restrict__ vv,
          float* __restrict__ x)
{
    extern __shared__ uint32_t smu[];
    uint32_t* Qs = smu;                // [128][40]  [q][csw(d>>1)]
    uint32_t* Ks = Qs + 128 * ALDA;    // [64][40]   [key][csw(d>>1)]
    uint32_t* Vs = Ks + 64 * ALDA;     // [64][40]   [d][csw(key>>1)]
    uint32_t* Ps = Vs + 64 * ALDA;     // [128][40]  [q][csw(key>>1)]

    const int tid  = threadIdx.x;
    const int wid  = tid >> 5;
    const int lane = tid & 31;
    const int lrow = lane >> 2;
    const int lcol = lane & 3;
    const int bh   = blockIdx.y;
    const int q0   = blockIdx.x * 128;

    const float* Abh = aw + (size_t)bh * NS * NDK;
    const float* Vbh = vv + (size_t)bh * NS * NDK;

    // Q tile: unit u: r=u>>3, b=(u&7)>>1, sub=u&1 -> d0=16b+4sub, col0=8b+4sub
    for (int i = 0; i < 4; i++) {
        const int u = tid + i * 256;
        const int r = u >> 3, b = (u & 7) >> 1, sub = u & 1;
        const int d0 = 16 * b + 4 * sub;
        const float4 v0 = *reinterpret_cast<const float4*>(
            &Abh[(size_t)(q0 + r) * NDK + d0]);
        const float4 v1 = *reinterpret_cast<const float4*>(
            &Abh[(size_t)(q0 + r) * NDK + d0 + 8]);
        uint32_t* dq = &Qs[r * ALDA + 8 * b + 4 * sub];
        *reinterpret_cast<uint2*>(dq + 0) =
            make_uint2(h2pack(v0.x, v0.y), h2pack(v1.x, v1.y));
        *reinterpret_cast<uint2*>(dq + 2) =
            make_uint2(h2pack(v0.z, v0.w), h2pack(v1.z, v1.w));
    }

    float m_[2], l_[2], o[8][4];
    m_[0] = m_[1] = -CUDART_INF_F;
    l_[0] = l_[1] = 0.f;
#pragma unroll
    for (int nf = 0; nf < 8; nf++)
#pragma unroll
        for (int r = 0; r < 4; r++) o[nf][r] = 0.f;

    const int mrow = wid * 16 + lrow;

    for (int k0 = 0; k0 < NS; k0 += 64) {
        // K tile
        for (int i = 0; i < 2; i++) {
            const int u = tid + i * 256;
            const int r = u >> 3, b = (u & 7) >> 1, sub = u & 1;
            const int d0 = 16 * b + 4 * sub;
            const float4 v0 = *reinterpret_cast<const float4*>(
                &Abh[(size_t)(k0 + r) * NDK + d0]);
            const float4 v1 = *reinterpret_cast<const float4*>(
                &Abh[(size_t)(k0 + r) * NDK + d0 + 8]);
            uint32_t* dk = &Ks[r * ALDA + 8 * b + 4 * sub];
            *reinterpret_cast<uint2*>(dk + 0) =
                make_uint2(h2pack(v0.x, v0.y), h2pack(v1.x, v1.y));
            *reinterpret_cast<uint2*>(dk + 2) =
                make_uint2(h2pack(v0.z, v0.w), h2pack(v1.z, v1.w));
        }
        // V tile transposed: unit u: c2=u&31 (key pair), d4=u>>5
        for (int i = 0; i < 2; i++) {
            const int u = tid + i * 256;
            const int c2 = u & 31, d4 = u >> 5;
            const float4 w0 = *reinterpret_cast<const float4*>(
                &Vbh[(size_t)(k0 + 2 * c2) * NDK + 4 * d4]);
            const float4 w1 = *reinterpret_cast<const float4*>(
                &Vbh[(size_t)(k0 + 2 * c2 + 1) * NDK + 4 * d4]);
            const int cc = csw(c2);
#pragma unroll
            for (int e = 0; e < 4; e++)
                Vs[(4 * d4 + e) * ALDA + cc] = h2pack(f4e(w0, e), f4e(w1, e));
        }
        __syncthreads();

        // --- S = Q @ K^T ---
        float s[8][4];
#pragma unroll
        for (int nf = 0; nf < 8; nf++)
#pragma unroll
            for (int r = 0; r < 4; r++) s[nf][r] = 0.f;

#pragma unroll
        for (int kb = 0; kb < 4; kb++) {
            const int col = 8 * kb + 2 * lcol;
            const uint2 p0 = *reinterpret_cast<const uint2*>(&Qs[mrow * ALDA + col]);
            const uint2 p1 = *reinterpret_cast<const uint2*>(&Qs[(mrow + 8) * ALDA + col]);
#pragma unroll
            for (int nf = 0; nf < 8; nf++) {
                const uint2 q = *reinterpret_cast<const uint2*>(
                    &Ks[(nf * 8 + lrow) * ALDA + col]);
                mma16(s[nf], p0.x, p1.x, p0.y, p1.y, q.x, q.y);
            }
        }

        // --- online softmax ---
#pragma unroll
        for (int hh = 0; hh < 2; hh++) {
            float rm = -CUDART_INF_F;
#pragma unroll
            for (int nf = 0; nf < 8; nf++) {
                s[nf][2 * hh + 0] *= 0.125f;
                s[nf][2 * hh + 1] *= 0.125f;
                rm = fmaxf(rm, fmaxf(s[nf][2 * hh + 0], s[nf][2 * hh + 1]));
            }
            rm = fmaxf(rm, __shfl_xor_sync(0xffffffffu, rm, 1));
            rm = fmaxf(rm, __shfl_xor_sync(0xffffffffu, rm, 2));

            const float mnew  = fmaxf(m_[hh], rm);
            const float alpha = __expf(m_[hh] - mnew);
            float ps = 0.f;
#pragma unroll
            for (int nf = 0; nf < 8; nf++) {
                s[nf][2 * hh + 0] = __expf(s[nf][2 * hh + 0] - mnew);
                s[nf][2 * hh + 1] = __expf(s[nf][2 * hh + 1] - mnew);
                ps += s[nf][2 * hh + 0] + s[nf][2 * hh + 1];
            }
            ps += __shfl_xor_sync(0xffffffffu, ps, 1);
            ps += __shfl_xor_sync(0xffffffffu, ps, 2);

            l_[hh] = l_[hh] * alpha + ps;
            m_[hh] = mnew;
#pragma unroll
            for (int nf = 0; nf < 8; nf++) {
                o[nf][2 * hh + 0] *= alpha;
                o[nf][2 * hh + 1] *= alpha;
            }
        }

        // --- stage P (half2): col = csw(nf*4+lcol) = 8*(nf>>1)+2*lcol+(nf&1) ---
#pragma unroll
        for (int nf = 0; nf < 8; nf++) {
            const int colp = 8 * (nf >> 1) + 2 * lcol + (nf & 1);
            Ps[mrow * ALDA + colp]       = h2pack(s[nf][0], s[nf][1]);
            Ps[(mrow + 8) * ALDA + colp] = h2pack(s[nf][2], s[nf][3]);
        }
        __syncwarp();

        // --- O += P @ V ---
#pragma unroll
        for (int kb = 0; kb < 4; kb++) {
            const int col = 8 * kb + 2 * lcol;
            const uint2 p0 = *reinterpret_cast<const uint2*>(&Ps[mrow * ALDA + col]);
            const uint2 p1 = *reinterpret_cast<const uint2*>(&Ps[(mrow + 8) * ALDA + col]);
#pragma unroll
            for (int nf = 0; nf < 8; nf++) {
                const uint2 q = *reinterpret_cast<const uint2*>(
                    &Vs[(nf * 8 + lrow) * ALDA + col]);
                mma16(o[nf], p0.x, p1.x, p0.y, p1.y, q.x, q.y);
            }
        }
        __syncthreads();
    }

    const int b = bh >> 3, h = bh & 7;
#pragma unroll
    for (int hh = 0; hh < 2; hh++) {
        const int r = q0 + mrow + hh * 8;
        const float inv = 1.f / l_[hh];
#pragma unroll
        for (int nf = 0; nf < 8; nf++) {
            const int d = nf * 8 + 2 * lcol;
            *reinterpret_cast<float2*>(
                &x[((size_t)(b * NS + r)) * NF + h * NDK + d]) =
                make_float2(o[nf][2 * hh + 0] * inv, o[nf][2 * hh + 1] * inv);
        }
    }
}

// ---------------------------------------------------------------------------
extern "C" void kernel_launch(void* const* d_in, const int* in_sizes, int n_in,
                              void* d_out, int out_size)
{
    const float* query = (const float*)d_in[0];
    // d_in[1] = key_t (unused by the synthesizer module)
    const float* value = (const float*)d_in[2];
    const float* w1 = (const float*)d_in[3];
    const float* b1 = (const float*)d_in[4];
    const float* w2 = (const float*)d_in[5];
    const float* b2 = (const float*)d_in[6];
    const float* wv = (const float*)d_in[7];
    const float* bv = (const float*)d_in[8];
    const float* wo = (const float*)d_in[9];
    const float* bo = (const float*)d_in[10];
    float* out = (float*)d_out;

    float *ph, *paw, *pv, *px;
    cudaGetSymbolAddress((void**)&ph,  g_h);
    cudaGetSymbolAddress((void**)&paw, g_aw);
    cudaGetSymbolAddress((void**)&pv,  g_v);
    cudaGetSymbolAddress((void**)&px,  g_x);

    const dim3 blk(256);
    const int gemm_smem = 2 * 2 * 128 * GLDAH * 4;            // 49,152 B
    const int attn_smem = (128 + 64 + 64 + 128) * ALDA * 4;   // 61,440 B
    cudaFuncSetAttribute(hgemm<0>, cudaFuncAttributeMaxDynamicSharedMemorySize, gemm_smem);
    cudaFuncSetAttribute(hgemm<1>, cudaFuncAttributeMaxDynamicSharedMemorySize, gemm_smem);
    cudaFuncSetAttribute(hgemm<2>, cudaFuncAttributeMaxDynamicSharedMemorySize, gemm_smem);
    cudaFuncSetAttribute(attn_hmma, cudaFuncAttributeMaxDynamicSharedMemorySize, attn_smem);

    // 1) h = relu(q @ w1 + b1)
    hgemm<0><<<dim3(NHID / 128, NM / 128), blk, gemm_smem>>>(NM, NHID, NF, query, w1, b1, ph);
    // 2) aw = h @ w2 + b2 -> [B,H,S,dk]
    hgemm<1><<<dim3(NF / 128, NM / 128), blk, gemm_smem>>>(NM, NF, NHID, ph, w2, b2, paw);
    // 3) v = value @ wv + bv -> [B,H,S,dk]
    hgemm<1><<<dim3(NF / 128, NM / 128), blk, gemm_smem>>>(NM, NF, NF, value, wv, bv, pv);
    // 4) fp16 tensor-core flash attention -> x [B,S,F]
    attn_hmma<<<dim3(NS / 128, NB * NH), blk, attn_smem>>>(paw, pv, px);
    // 5) out = x @ wo + bo
    hgemm<2><<<dim3(NF / 128, NM / 128), blk, gemm_smem>>>(NM, NF, NF, px, wo, bo, out);
}

// round 11
// speedup vs baseline: 5.0142x; 1.1450x over previous
#include <cuda_runtime.h>
#include <cuda_fp16.h>
#include <math_constants.h>
#include <cstdint>

// Problem constants
#define NB    8
#define NS    1024
#define NF    512
#define NHID  1024
#define NH    8
#define NDK   64
#define NM    (NB * NS)        // 8192 token rows

// Scratch (allocation-free: __device__ globals), fp16 pipeline
__device__ __half g_qh  [NM * NF];           // query fp16
__device__ __half g_valh[NM * NF];           // value fp16
__device__ __half g_w1h [NF * NHID];
__device__ __half g_w2h [NHID * NF];
__device__ __half g_wvh [NF * NF];
__device__ __half g_woh [NF * NF];
__device__ __half g_hh  [NM * NHID];         // relu(q@w1+b1)
__device__ __half g_awh [NB * NH * NS * NDK];// [B,H,S,dk]
__device__ __half g_vh  [NB * NH * NS * NDK];// [B,H,S,dk]
__device__ __half g_xh  [NM * NF];           // attention out [B,S,F]

__device__ __forceinline__ uint32_t h2pack(float a, float b) {
    __half2 h = __floats2half2_rn(a, b);
    return reinterpret_cast<uint32_t&>(h);
}
__device__ __forceinline__ uint32_t hh2u(__half a, __half b) {
    __half2 h = __halves2half2(a, b);
    return reinterpret_cast<uint32_t&>(h);
}
// e-th half / j-th half2 of a uint4 (8 halves)
__device__ __forceinline__ __half u4h(const uint4& v, int e) {
    return reinterpret_cast<const __half*>(&v)[e];
}
__device__ __forceinline__ uint32_t u4h2(const uint4& v, int j) {
    return reinterpret_cast<const uint32_t*>(&v)[j];
}

__device__ __forceinline__ void mma16(float* c,
                                      uint32_t a0, uint32_t a1, uint32_t a2, uint32_t a3,
                                      uint32_t b0, uint32_t b1) {
    asm volatile(
        "mma.sync.aligned.m16n8k16.row.col.f32.f16.f16.f32 "
        "{%0,%1,%2,%3}, {%4,%5,%6,%7}, {%8,%9}, {%0,%1,%2,%3};"
        : "+f"(c[0]), "+f"(c[1]), "+f"(c[2]), "+f"(c[3])
        : "r"(a0), "r"(a1), "r"(a2), "r"(a3), "r"(b0), "r"(b1));
}

// ---------------------------------------------------------------------------
// fp32 -> fp16 conversion (n % 4 == 0)
// ---------------------------------------------------------------------------
__global__ void __launch_bounds__(256)
f2h_kernel(const float* __restrict__ src, __half* __restrict__ dst, int n)
{
    const int i = (blockIdx.x * 256 + threadIdx.x) * 4;
    if (i < n) {
        const float4 v = *reinterpret_cast<const float4*>(src + i);
        *reinterpret_cast<uint2*>(dst + i) =
            make_uint2(h2pack(v.x, v.y), h2pack(v.z, v.w));
    }
}

// ---------------------------------------------------------------------------
// FP16-in GEMM, double-buffered + register prefetch.
// CTA tile 128x128, BK=32 halves, 256 threads = 8 warps (2x4), warp 64x32.
// Smem unit = half2, LDA=24 u32. Fragment loop identical to validated R8.
// B rows XOR-swizzled by col ^= 2*((nrow>>3)&7) (store AND fragment load).
// MODE 0: relu -> half [M,N] | MODE 1: half scatter [B,H,S,dk] | MODE 2: float [M,N]
// ---------------------------------------------------------------------------
#define GLDAH 24

template <int MODE>
__global__ void __launch_bounds__(256)
hgemm(int M, int N, int K,
      const __half* __restrict__ A,
      const __half* __restrict__ W,
      const float* __restrict__ bias,
      void* __restrict__ outv)
{
    extern __shared__ uint32_t sg[];
    uint32_t (*As2)[GLDAH] = reinterpret_cast<uint32_t(*)[GLDAH]>(sg);
    uint32_t (*Bs2)[GLDAH] = reinterpret_cast<uint32_t(*)[GLDAH]>(sg + 2 * 128 * GLDAH);

    const int tid  = threadIdx.x;
    const int bm   = blockIdx.y * 128;
    const int bn   = blockIdx.x * 128;
    const int wid  = tid >> 5;
    const int lane = tid & 31;
    const int wr   = wid & 1;
    const int wc   = wid >> 1;
    const int lrow = lane >> 2;
    const int lcol = lane & 3;

    // A stager: row = tid>>1, seg s = tid&1 -> halves [16s,16s+16)  (BK=32: complete)
    const int a_r = tid >> 1;
    const int a_s = tid & 1;
    // B stager (tid < 128): n8 = tid&15 (8 n's), kq = tid>>4 (0..7)
    //   p = (kq>>2)*8 + (kq&3) in {0..3, 8..11}; k rows 2p,2p+1,2p+8,2p+9
    const int b_n8 = tid & 15;
    const int b_kq = tid >> 4;
    const int b_p  = ((b_kq >> 2) << 3) + (b_kq & 3);
    const int b_cb = ((b_p & ~7) + 2 * (b_p & 3)) ^ (2 * (b_n8 & 7));

    uint4 pa[2], pbw[4];

    auto load_tiles = [&](int k0) {
        const __half* p = &A[(size_t)(bm + a_r) * K + k0 + 16 * a_s];
        pa[0] = *reinterpret_cast<const uint4*>(p);
        pa[1] = *reinterpret_cast<const uint4*>(p + 8);
        if (tid < 128) {
            const __half* q = &W[(size_t)(k0 + 2 * b_p) * N + bn + 8 * b_n8];
            pbw[0] = *reinterpret_cast<const uint4*>(q);
            pbw[1] = *reinterpret_cast<const uint4*>(q + (size_t)N);
            pbw[2] = *reinterpret_cast<const uint4*>(q + (size_t)8 * N);
            pbw[3] = *reinterpret_cast<const uint4*>(q + (size_t)9 * N);
        }
    };
    auto store_tiles = [&](int buf) {
        uint32_t* da = &As2[buf * 128 + a_r][8 * a_s];
#pragma unroll
        for (int j = 0; j < 4; j++)
            *reinterpret_cast<uint2*>(da + 2 * j) =
                make_uint2(u4h2(pa[0], j), u4h2(pa[1], j));
        if (tid < 128) {
#pragma unroll
            for (int e = 0; e < 8; e++)
                *reinterpret_cast<uint2*>(&Bs2[buf * 128 + 8 * b_n8 + e][b_cb]) =
                    make_uint2(hh2u(u4h(pbw[0], e), u4h(pbw[1], e)),
                               hh2u(u4h(pbw[2], e), u4h(pbw[3], e)));
        }
    };

    float c[4][4][4];
#pragma unroll
    for (int mf = 0; mf < 4; mf++)
#pragma unroll
        for (int nf = 0; nf < 4; nf++)
#pragma unroll
            for (int r = 0; r < 4; r++) c[mf][nf][r] = 0.f;

    const int T = K >> 5;
    load_tiles(0);
    store_tiles(0);
    load_tiles(32);
    __syncthreads();

    int cur = 0;
    for (int t = 0; t < T; t++) {
        if (t + 1 < T) {
            store_tiles(cur ^ 1);
            if (t + 2 < T) load_tiles((t + 2) << 5);
        }
#pragma unroll
        for (int kb = 0; kb < 2; kb++) {
            const int col = 8 * kb + 2 * lcol;
            uint32_t af[4][4];
#pragma unroll
            for (int mf = 0; mf < 4; mf++) {
                const int m = cur * 128 + wr * 64 + mf * 16 + lrow;
                const uint2 p0 = *reinterpret_cast<const uint2*>(&As2[m][col]);
                const uint2 p1 = *reinterpret_cast<const uint2*>(&As2[m + 8][col]);
                af[mf][0] = p0.x; af[mf][2] = p0.y;
                af[mf][1] = p1.x; af[mf][3] = p1.y;
            }
            uint32_t bf[4][2];
#pragma unroll
            for (int nf = 0; nf < 4; nf++) {
                const int nl = wc * 32 + nf * 8 + lrow;
                const int cb = col ^ (2 * ((wc * 4 + nf) & 7));
                const uint2 q = *reinterpret_cast<const uint2*>(&Bs2[cur * 128 + nl][cb]);
                bf[nf][0] = q.x; bf[nf][1] = q.y;
            }
#pragma unroll
            for (int mf = 0; mf < 4; mf++)
#pragma unroll
                for (int nf = 0; nf < 4; nf++)
                    mma16(c[mf][nf], af[mf][0], af[mf][1], af[mf][2], af[mf][3],
                          bf[nf][0], bf[nf][1]);
        }
        __syncthreads();
        cur ^= 1;
    }

#pragma unroll
    for (int mf = 0; mf < 4; mf++) {
#pragma unroll
        for (int nf = 0; nf < 4; nf++) {
            const int row0 = bm + wr * 64 + mf * 16 + lrow;
            const int col0 = bn + wc * 32 + nf * 8 + 2 * lcol;
            const float bsum0 = bias[col0], bsum1 = bias[col0 + 1];
#pragma unroll
            for (int half = 0; half < 2; half++) {
                const int m = row0 + half * 8;
                float v0 = c[mf][nf][half * 2 + 0] + bsum0;
                float v1 = c[mf][nf][half * 2 + 1] + bsum1;
                if (MODE == 0) {
                    v0 = fmaxf(v0, 0.f); v1 = fmaxf(v1, 0.f);
                    *reinterpret_cast<uint32_t*>(
                        &((__half*)outv)[(size_t)m * N + col0]) = h2pack(v0, v1);
                } else if (MODE == 1) {
                    const int b = m >> 10, s = m & 1023;
                    const int h = col0 >> 6, d = col0 & 63;
                    *reinterpret_cast<uint32_t*>(
                        &((__half*)outv)[((((size_t)b * NH + h) * NS + s) * NDK) + d]) =
                        h2pack(v0, v1);
                } else {
                    *reinterpret_cast<float2*>(
                        &((float*)outv)[(size_t)m * N + col0]) = make_float2(v0, v1);
                }
            }
        }
    }
}

// ---------------------------------------------------------------------------
// FP16 flash attention. CTA: 128 q x dk=64; 64-key tiles; 8 warps x 16 q rows.
// Q stager = 2 iters x 256 thr (r=u>>2, s=u&3, 4 segs/row);
// K stager = 2 iters x 128 thr (r=u>>2, s=u&3). Full 64-half rows.
// Vs rows XOR-swizzled by col ^= 2*((drow>>3)&7) (store AND fragment load).
// ---------------------------------------------------------------------------
#define ALDA 40

__global__ void __launch_bounds__(256)
attn_hmma(const __half* __restrict__ aw,
          const __half* __restrict__ vv,
          __half* __restrict__ x)
{
    extern __shared__ uint32_t smu[];
    uint32_t* Qs = smu;                // [128][40]  [q][csw(d2)]
    uint32_t* Ks = Qs + 128 * ALDA;    // [64][40]   [key][csw(d2)]
    uint32_t* Vs = Ks + 64 * ALDA;     // [64][40]   [d][csw(key2)^swz]
    uint32_t* Ps = Vs + 64 * ALDA;     // [128][40]  [q][csw(key2)]

    const int tid  = threadIdx.x;
    const int wid  = tid >> 5;
    const int lane = tid & 31;
    const int lrow = lane >> 2;
    const int lcol = lane & 3;
    const int bh   = blockIdx.y;
    const int q0   = blockIdx.x * 128;

    const __half* Abh = aw + (size_t)bh * NS * NDK;
    const __half* Vbh = vv + (size_t)bh * NS * NDK;

    // Q stager: 512 units = 128 rows x 4 segs of 16 halves
#pragma unroll
    for (int i = 0; i < 2; i++) {
        const int u = tid + i * 256;
        const int r = u >> 2, s = u & 3;
        const __half* p = &Abh[(size_t)(q0 + r) * NDK + 16 * s];
        const uint4 ua = *reinterpret_cast<const uint4*>(p);
        const uint4 ub = *reinterpret_cast<const uint4*>(p + 8);
        uint32_t* dq = &Qs[r * ALDA + 8 * s];
#pragma unroll
        for (int j = 0; j < 4; j++)
            *reinterpret_cast<uint2*>(dq + 2 * j) =
                make_uint2(u4h2(ua, j), u4h2(ub, j));
    }

    float m_[2], l_[2], o[8][4];
    m_[0] = m_[1] = -CUDART_INF_F;
    l_[0] = l_[1] = 0.f;
#pragma unroll
    for (int nf = 0; nf < 8; nf++)
#pragma unroll
        for (int r = 0; r < 4; r++) o[nf][r] = 0.f;

    const int mrow = wid * 16 + lrow;

    // V stager constants (threads 128..255): d8 = t2&7, pq = t2>>3 (0..15)
    const int v_t2 = tid - 128;
    const int v_d8 = v_t2 & 7;
    const int v_pq = v_t2 >> 3;
    const int v_p  = ((v_pq >> 2) << 3) + (v_pq & 3);   // {0..3,8..11,16..19,24..27}
    const int v_cb = ((v_p & ~7) + 2 * (v_p & 3)) ^ (2 * (v_d8 & 7));

    for (int k0 = 0; k0 < NS; k0 += 64) {
        if (tid < 128) {
            // K stager: 256 units = 64 rows x 4 segs of 16 halves
#pragma unroll
            for (int i = 0; i < 2; i++) {
                const int u = tid + i * 128;
                const int r = u >> 2, s = u & 3;
                const __half* p = &Abh[(size_t)(k0 + r) * NDK + 16 * s];
                const uint4 ua = *reinterpret_cast<const uint4*>(p);
                const uint4 ub = *reinterpret_cast<const uint4*>(p + 8);
                uint32_t* dk = &Ks[r * ALDA + 8 * s];
#pragma unroll
                for (int j = 0; j < 4; j++)
                    *reinterpret_cast<uint2*>(dk + 2 * j) =
                        make_uint2(u4h2(ua, j), u4h2(ub, j));
            }
        } else {
            // V stager: keys {2p,2p+1,2p+8,2p+9} x 8 d's, transposed into Vs
            const __half* q = &Vbh[(size_t)(k0 + 2 * v_p) * NDK + 8 * v_d8];
            const uint4 ua = *reinterpret_cast<const uint4*>(q);
            const uint4 ub = *reinterpret_cast<const uint4*>(q + (size_t)NDK);
            const uint4 uc = *reinterpret_cast<const uint4*>(q + (size_t)8 * NDK);
            const uint4 ud = *reinterpret_cast<const uint4*>(q + (size_t)9 * NDK);
#pragma unroll
            for (int e = 0; e < 8; e++)
                *reinterpret_cast<uint2*>(&Vs[(8 * v_d8 + e) * ALDA + v_cb]) =
                    make_uint2(hh2u(u4h(ua, e), u4h(ub, e)),
                               hh2u(u4h(uc, e), u4h(ud, e)));
        }
        __syncthreads();

        // --- S = Q @ K^T ---
        float s[8][4];
#pragma unroll
        for (int nf = 0; nf < 8; nf++)
#pragma unroll
            for (int r = 0; r < 4; r++) s[nf][r] = 0.f;

#pragma unroll
        for (int kb = 0; kb < 4; kb++) {
            const int col = 8 * kb + 2 * lcol;
            const uint2 p0 = *reinterpret_cast<const uint2*>(&Qs[mrow * ALDA + col]);
            const uint2 p1 = *reinterpret_cast<const uint2*>(&Qs[(mrow + 8) * ALDA + col]);
#pragma unroll
            for (int nf = 0; nf < 8; nf++) {
                const uint2 q = *reinterpret_cast<const uint2*>(
                    &Ks[(nf * 8 + lrow) * ALDA + col]);
                mma16(s[nf], p0.x, p1.x, p0.y, p1.y, q.x, q.y);
            }
        }

        // --- online softmax ---
#pragma unroll
        for (int hh = 0; hh < 2; hh++) {
            float rm = -CUDART_INF_F;
#pragma unroll
            for (int nf = 0; nf < 8; nf++) {
                s[nf][2 * hh + 0] *= 0.125f;
                s[nf][2 * hh + 1] *= 0.125f;
                rm = fmaxf(rm, fmaxf(s[nf][2 * hh + 0], s[nf][2 * hh + 1]));
            }
            rm = fmaxf(rm, __shfl_xor_sync(0xffffffffu, rm, 1));
            rm = fmaxf(rm, __shfl_xor_sync(0xffffffffu, rm, 2));

            const float mnew  = fmaxf(m_[hh], rm);
            const float alpha = __expf(m_[hh] - mnew);
            float ps = 0.f;
#pragma unroll
            for (int nf = 0; nf < 8; nf++) {
                s[nf][2 * hh + 0] = __expf(s[nf][2 * hh + 0] - mnew);
                s[nf][2 * hh + 1] = __expf(s[nf][2 * hh + 1] - mnew);
                ps += s[nf][2 * hh + 0] + s[nf][2 * hh + 1];
            }
            ps += __shfl_xor_sync(0xffffffffu, ps, 1);
            ps += __shfl_xor_sync(0xffffffffu, ps, 2);

            l_[hh] = l_[hh] * alpha + ps;
            m_[hh] = mnew;
#pragma unroll
            for (int nf = 0; nf < 8; nf++) {
                o[nf][2 * hh + 0] *= alpha;
                o[nf][2 * hh + 1] *= alpha;
            }
        }

        // --- stage P (half2) ---
#pragma unroll
        for (int nf = 0; nf < 8; nf++) {
            const int colp = 8 * (nf >> 1) + 2 * lcol + (nf & 1);
            Ps[mrow * ALDA + colp]       = h2pack(s[nf][0], s[nf][1]);
            Ps[(mrow + 8) * ALDA + colp] = h2pack(s[nf][2], s[nf][3]);
        }
        __syncwarp();

        // --- O += P @ V ---
#pragma unroll
        for (int kb = 0; kb < 4; kb++) {
            const int col = 8 * kb + 2 * lcol;
            const uint2 p0 = *reinterpret_cast<const uint2*>(&Ps[mrow * ALDA + col]);
            const uint2 p1 = *reinterpret_cast<const uint2*>(&Ps[(mrow + 8) * ALDA + col]);
#pragma unroll
            for (int nf = 0; nf < 8; nf++) {
                const int cb = col ^ (2 * (nf & 7));
                const uint2 q = *reinterpret_cast<const uint2*>(
                    &Vs[(nf * 8 + lrow) * ALDA + cb]);
                mma16(o[nf], p0.x, p1.x, p0.y, p1.y, q.x, q.y);
            }
        }
        __syncthreads();
    }

    // Epilogue: x[b, s, h*64+d] = o / l  (half2 stores)
    const int b = bh >> 3, h = bh & 7;
#pragma unroll
    for (int hh = 0; hh < 2; hh++) {
        const int r = q0 + mrow + hh * 8;
        const float inv = 1.f / l_[hh];
#pragma unroll
        for (int nf = 0; nf < 8; nf++) {
            const int d = nf * 8 + 2 * lcol;
            *reinterpret_cast<uint32_t*>(
                &x[((size_t)(b * NS + r)) * NF + h * NDK + d]) =
                h2pack(o[nf][2 * hh + 0] * inv, o[nf][2 * hh + 1] * inv);
        }
    }
}

// ---------------------------------------------------------------------------
extern "C" void kernel_launch(void* const* d_in, const int* in_sizes, int n_in,
                              void* d_out, int out_size)
{
    const float* query = (const float*)d_in[0];
    // d_in[1] = key_t (unused by the synthesizer module)
    const float* value = (const float*)d_in[2];
    const float* w1 = (const float*)d_in[3];
    const float* b1 = (const float*)d_in[4];
    const float* w2 = (const float*)d_in[5];
    const float* b2 = (const float*)d_in[6];
    const float* wv = (const float*)d_in[7];
    const float* bv = (const float*)d_in[8];
    const float* wo = (const float*)d_in[9];
    const float* bo = (const float*)d_in[10];
    float* out = (float*)d_out;

    __half *qh, *valh, *w1h, *w2h, *wvh, *woh, *hh, *awh, *vh, *xh;
    cudaGetSymbolAddress((void**)&qh,   g_qh);
    cudaGetSymbolAddress((void**)&valh, g_valh);
    cudaGetSymbolAddress((void**)&w1h,  g_w1h);
    cudaGetSymbolAddress((void**)&w2h,  g_w2h);
    cudaGetSymbolAddress((void**)&wvh,  g_wvh);
    cudaGetSymbolAddress((void**)&woh,  g_woh);
    cudaGetSymbolAddress((void**)&hh,   g_hh);
    cudaGetSymbolAddress((void**)&awh,  g_awh);
    cudaGetSymbolAddress((void**)&vh,   g_vh);
    cudaGetSymbolAddress((void**)&xh,   g_xh);

    const dim3 blk(256);
    const int gemm_smem = 2 * 2 * 128 * GLDAH * 4;            // 49,152 B
    const int attn_smem = (128 + 64 + 64 + 128) * ALDA * 4;   // 61,440 B
    cudaFuncSetAttribute(hgemm<0>, cudaFuncAttributeMaxDynamicSharedMemorySize, gemm_smem);
    cudaFuncSetAttribute(hgemm<1>, cudaFuncAttributeMaxDynamicSharedMemorySize, gemm_smem);
    cudaFuncSetAttribute(hgemm<2>, cudaFuncAttributeMaxDynamicSharedMemorySize, gemm_smem);
    cudaFuncSetAttribute(attn_hmma, cudaFuncAttributeMaxDynamicSharedMemorySize, attn_smem);

    // 0) fp32 -> fp16 conversions
    f2h_kernel<<<(NM * NF) / 1024, blk>>>(query, qh, NM * NF);
    f2h_kernel<<<(NM * NF) / 1024, blk>>>(value, valh, NM * NF);
    f2h_kernel<<<(NF * NHID) / 1024, blk>>>(w1, w1h, NF * NHID);
    f2h_kernel<<<(NHID * NF) / 1024, blk>>>(w2, w2h, NHID * NF);
    f2h_kernel<<<(NF * NF) / 1024, blk>>>(wv, wvh, NF * NF);
    f2h_kernel<<<(NF * NF) / 1024, blk>>>(wo, woh, NF * NF);

    // 1) h = relu(q @ w1 + b1) -> half
    hgemm<0><<<dim3(NHID / 128, NM / 128), blk, gemm_smem>>>(NM, NHID, NF, qh, w1h, b1, hh);
    // 2) aw = h @ w2 + b2 -> half [B,H,S,dk]
    hgemm<1><<<dim3(NF / 128, NM / 128), blk, gemm_smem>>>(NM, NF, NHID, hh, w2h, b2, awh);
    // 3) v = value @ wv + bv -> half [B,H,S,dk]
    hgemm<1><<<dim3(NF / 128, NM / 128), blk, gemm_smem>>>(NM, NF, NF, valh, wvh, bv, vh);
    // 4) fp16 flash attention -> half x [B,S,F]
    attn_hmma<<<dim3(NS / 128, NB * NH), blk, attn_smem>>>(awh, vh, xh);
    // 5) out = x @ wo + bo -> float
    hgemm<2><<<dim3(NF / 128, NM / 128), blk, gemm_smem>>>(NM, NF, NF, xh, woh, bo, out);
}

// round 14
// speedup vs baseline: 5.2680x; 1.0506x over previous
#include <cuda_runtime.h>
#include <cuda_fp16.h>
#include <math_constants.h>
#include <cstdint>

// Problem constants
#define NB    8
#define NS    1024
#define NF    512
#define NHID  1024
#define NH    8
#define NDK   64
#define NM    (NB * NS)        // 8192 token rows

// Scratch (allocation-free: __device__ globals), fp16 pipeline
__device__ __half g_qh  [NM * NF];           // query fp16
__device__ __half g_valh[NM * NF];           // value fp16
__device__ __half g_w1h [NF * NHID];
__device__ __half g_w2h [NHID * NF];
__device__ __half g_wvh [NF * NF];
__device__ __half g_woh [NF * NF];
__device__ __half g_hh  [NM * NHID];         // relu(q@w1+b1)
__device__ __half g_awh [NB * NH * NS * NDK];// [B,H,S,dk]
__device__ __half g_vh  [NB * NH * NS * NDK];// [B,H,S,dk]
__device__ __half g_xh  [NM * NF];           // attention out [B,S,F]

__device__ __forceinline__ uint32_t h2pack(float a, float b) {
    __half2 h = __floats2half2_rn(a, b);
    return reinterpret_cast<uint32_t&>(h);
}
__device__ __forceinline__ uint32_t hh2u(__half a, __half b) {
    __half2 h = __halves2half2(a, b);
    return reinterpret_cast<uint32_t&>(h);
}
// e-th half / j-th half2 of a uint4 (8 halves)
__device__ __forceinline__ __half u4h(const uint4& v, int e) {
    return reinterpret_cast<const __half*>(&v)[e];
}
__device__ __forceinline__ uint32_t u4h2(const uint4& v, int j) {
    return reinterpret_cast<const uint32_t*>(&v)[j];
}
__device__ __forceinline__ float ex2(float x) {
    float y;
    asm("ex2.approx.f32 %0, %1;" : "=f"(y) : "f"(x));
    return y;
}

__device__ __forceinline__ void mma16(float* c,
                                      uint32_t a0, uint32_t a1, uint32_t a2, uint32_t a3,
                                      uint32_t b0, uint32_t b1) {
    asm volatile(
        "mma.sync.aligned.m16n8k16.row.col.f32.f16.f16.f32 "
        "{%0,%1,%2,%3}, {%4,%5,%6,%7}, {%8,%9}, {%0,%1,%2,%3};"
        : "+f"(c[0]), "+f"(c[1]), "+f"(c[2]), "+f"(c[3])
        : "r"(a0), "r"(a1), "r"(a2), "r"(a3), "r"(b0), "r"(b1));
}

// ---------------------------------------------------------------------------
// fp32 -> fp16 conversion (n % 4 == 0)
// ---------------------------------------------------------------------------
__global__ void __launch_bounds__(256)
f2h_kernel(const float* __restrict__ src, __half* __restrict__ dst, int n)
{
    const int i = (blockIdx.x * 256 + threadIdx.x) * 4;
    if (i < n) {
        const float4 v = *reinterpret_cast<const float4*>(src + i);
        *reinterpret_cast<uint2*>(dst + i) =
            make_uint2(h2pack(v.x, v.y), h2pack(v.z, v.w));
    }
}

// ---------------------------------------------------------------------------
// FP16-in GEMM, double-buffered + register prefetch (unchanged from R11 pass).
// ---------------------------------------------------------------------------
#define GLDAH 24

template <int MODE>
__global__ void __launch_bounds__(256)
hgemm(int M, int N, int K,
      const __half* __restrict__ A,
      const __half* __restrict__ W,
      const float* __restrict__ bias,
      void* __restrict__ outv)
{
    extern __shared__ uint32_t sg[];
    uint32_t (*As2)[GLDAH] = reinterpret_cast<uint32_t(*)[GLDAH]>(sg);
    uint32_t (*Bs2)[GLDAH] = reinterpret_cast<uint32_t(*)[GLDAH]>(sg + 2 * 128 * GLDAH);

    const int tid  = threadIdx.x;
    const int bm   = blockIdx.y * 128;
    const int bn   = blockIdx.x * 128;
    const int wid  = tid >> 5;
    const int lane = tid & 31;
    const int wr   = wid & 1;
    const int wc   = wid >> 1;
    const int lrow = lane >> 2;
    const int lcol = lane & 3;

    const int a_r = tid >> 1;
    const int a_s = tid & 1;
    const int b_n8 = tid & 15;
    const int b_kq = tid >> 4;
    const int b_p  = ((b_kq >> 2) << 3) + (b_kq & 3);
    const int b_cb = ((b_p & ~7) + 2 * (b_p & 3)) ^ (2 * (b_n8 & 7));

    uint4 pa[2], pbw[4];

    auto load_tiles = [&](int k0) {
        const __half* p = &A[(size_t)(bm + a_r) * K + k0 + 16 * a_s];
        pa[0] = *reinterpret_cast<const uint4*>(p);
        pa[1] = *reinterpret_cast<const uint4*>(p + 8);
        if (tid < 128) {
            const __half* q = &W[(size_t)(k0 + 2 * b_p) * N + bn + 8 * b_n8];
            pbw[0] = *reinterpret_cast<const uint4*>(q);
            pbw[1] = *reinterpret_cast<const uint4*>(q + (size_t)N);
            pbw[2] = *reinterpret_cast<const uint4*>(q + (size_t)8 * N);
            pbw[3] = *reinterpret_cast<const uint4*>(q + (size_t)9 * N);
        }
    };
    auto store_tiles = [&](int buf) {
        uint32_t* da = &As2[buf * 128 + a_r][8 * a_s];
#pragma unroll
        for (int j = 0; j < 4; j++)
            *reinterpret_cast<uint2*>(da + 2 * j) =
                make_uint2(u4h2(pa[0], j), u4h2(pa[1], j));
        if (tid < 128) {
#pragma unroll
            for (int e = 0; e < 8; e++)
                *reinterpret_cast<uint2*>(&Bs2[buf * 128 + 8 * b_n8 + e][b_cb]) =
                    make_uint2(hh2u(u4h(pbw[0], e), u4h(pbw[1], e)),
                               hh2u(u4h(pbw[2], e), u4h(pbw[3], e)));
        }
    };

    float c[4][4][4];
#pragma unroll
    for (int mf = 0; mf < 4; mf++)
#pragma unroll
        for (int nf = 0; nf < 4; nf++)
#pragma unroll
            for (int r = 0; r < 4; r++) c[mf][nf][r] = 0.f;

    const int T = K >> 5;
    load_tiles(0);
    store_tiles(0);
    load_tiles(32);
    __syncthreads();

    int cur = 0;
    for (int t = 0; t < T; t++) {
        if (t + 1 < T) {
            store_tiles(cur ^ 1);
            if (t + 2 < T) load_tiles((t + 2) << 5);
        }
#pragma unroll
        for (int kb = 0; kb < 2; kb++) {
            const int col = 8 * kb + 2 * lcol;
            uint32_t af[4][4];
#pragma unroll
            for (int mf = 0; mf < 4; mf++) {
                const int m = cur * 128 + wr * 64 + mf * 16 + lrow;
                const uint2 p0 = *reinterpret_cast<const uint2*>(&As2[m][col]);
                const uint2 p1 = *reinterpret_cast<const uint2*>(&As2[m + 8][col]);
                af[mf][0] = p0.x; af[mf][2] = p0.y;
                af[mf][1] = p1.x; af[mf][3] = p1.y;
            }
            uint32_t bf[4][2];
#pragma unroll
            for (int nf = 0; nf < 4; nf++) {
                const int nl = wc * 32 + nf * 8 + lrow;
                const int cb = col ^ (2 * ((wc * 4 + nf) & 7));
                const uint2 q = *reinterpret_cast<const uint2*>(&Bs2[cur * 128 + nl][cb]);
                bf[nf][0] = q.x; bf[nf][1] = q.y;
            }
#pragma unroll
            for (int mf = 0; mf < 4; mf++)
#pragma unroll
                for (int nf = 0; nf < 4; nf++)
                    mma16(c[mf][nf], af[mf][0], af[mf][1], af[mf][2], af[mf][3],
                          bf[nf][0], bf[nf][1]);
        }
        __syncthreads();
        cur ^= 1;
    }

#pragma unroll
    for (int mf = 0; mf < 4; mf++) {
#pragma unroll
        for (int nf = 0; nf < 4; nf++) {
            const int row0 = bm + wr * 64 + mf * 16 + lrow;
            const int col0 = bn + wc * 32 + nf * 8 + 2 * lcol;
            const float bsum0 = bias[col0], bsum1 = bias[col0 + 1];
#pragma unroll
            for (int half = 0; half < 2; half++) {
                const int m = row0 + half * 8;
                float v0 = c[mf][nf][half * 2 + 0] + bsum0;
                float v1 = c[mf][nf][half * 2 + 1] + bsum1;
                if (MODE == 0) {
                    v0 = fmaxf(v0, 0.f); v1 = fmaxf(v1, 0.f);
                    *reinterpret_cast<uint32_t*>(
                        &((__half*)outv)[(size_t)m * N + col0]) = h2pack(v0, v1);
                } else if (MODE == 1) {
                    const int b = m >> 10, s = m & 1023;
                    const int h = col0 >> 6, d = col0 & 63;
                    *reinterpret_cast<uint32_t*>(
                        &((__half*)outv)[((((size_t)b * NH + h) * NS + s) * NDK) + d]) =
                        h2pack(v0, v1);
                } else {
                    *reinterpret_cast<float2*>(
                        &((float*)outv)[(size_t)m * N + col0]) = make_float2(v0, v1);
                }
            }
        }
    }
}

// ---------------------------------------------------------------------------
// FP16 flash attention, v2b (bisect of R12):
//  - register-direct P (S C-fragments ARE the P A-fragments; Ps smem deleted)
//  - SINGLE-buffer K/V with register prefetch: tile t+1 loads issue before
//    tile t's compute; stored to smem after a sync. Two syncs per tile.
//  - softmax in exp2 domain
// CTA: 128 q x dk=64; 16 x 64-key tiles; 8 warps x 16 q rows.
// Smem: Qs[128][40] + Ks[64][40] + Vs[64][40] = 40,960 B -> 2 CTAs/SM.
// ---------------------------------------------------------------------------
#define ALDA 40

__global__ void __launch_bounds__(256, 2)
attn_hmma(const __half* __restrict__ aw,
          const __half* __restrict__ vv,
          __half* __restrict__ x)
{
    extern __shared__ uint32_t smu[];
    uint32_t* Qs = smu;                // [128][40]  [q][csw(d2)]
    uint32_t* Ks = Qs + 128 * ALDA;    // [64][40]   [key][csw(d2)]
    uint32_t* Vs = Ks + 64 * ALDA;     // [64][40]   [d][csw(key2)^swz]

    const int tid  = threadIdx.x;
    const int wid  = tid >> 5;
    const int lane = tid & 31;
    const int lrow = lane >> 2;
    const int lcol = lane & 3;
    const int bh   = blockIdx.y;
    const int q0   = blockIdx.x * 128;

    const __half* Abh = aw + (size_t)bh * NS * NDK;
    const __half* Vbh = vv + (size_t)bh * NS * NDK;

    // Q stager: 512 units = 128 rows x 4 segs of 16 halves
#pragma unroll
    for (int i = 0; i < 2; i++) {
        const int u = tid + i * 256;
        const int r = u >> 2, s = u & 3;
        const __half* p = &Abh[(size_t)(q0 + r) * NDK + 16 * s];
        const uint4 ua = *reinterpret_cast<const uint4*>(p);
        const uint4 ub = *reinterpret_cast<const uint4*>(p + 8);
        uint32_t* dq = &Qs[r * ALDA + 8 * s];
#pragma unroll
        for (int j = 0; j < 4; j++)
            *reinterpret_cast<uint2*>(dq + 2 * j) =
                make_uint2(u4h2(ua, j), u4h2(ub, j));
    }

    // V stager constants (threads 128..255)
    const int v_t2 = tid - 128;
    const int v_d8 = v_t2 & 7;
    const int v_pq = v_t2 >> 3;
    const int v_p  = ((v_pq >> 2) << 3) + (v_pq & 3);
    const int v_cb = ((v_p & ~7) + 2 * (v_p & 3)) ^ (2 * (v_d8 & 7));

    uint4 kv[4];
    auto load_kv = [&](int k0) {
        if (tid < 128) {
#pragma unroll
            for (int i = 0; i < 2; i++) {
                const int u = tid + i * 128;
                const int r = u >> 2, s = u & 3;
                const __half* p = &Abh[(size_t)(k0 + r) * NDK + 16 * s];
                kv[2 * i]     = *reinterpret_cast<const uint4*>(p);
                kv[2 * i + 1] = *reinterpret_cast<const uint4*>(p + 8);
            }
        } else {
            const __half* q = &Vbh[(size_t)(k0 + 2 * v_p) * NDK + 8 * v_d8];
            kv[0] = *reinterpret_cast<const uint4*>(q);
            kv[1] = *reinterpret_cast<const uint4*>(q + (size_t)NDK);
            kv[2] = *reinterpret_cast<const uint4*>(q + (size_t)8 * NDK);
            kv[3] = *reinterpret_cast<const uint4*>(q + (size_t)9 * NDK);
        }
    };
    auto store_kv = [&]() {
        if (tid < 128) {
#pragma unroll
            for (int i = 0; i < 2; i++) {
                const int u = tid + i * 128;
                const int r = u >> 2, s = u & 3;
                uint32_t* dk = &Ks[r * ALDA + 8 * s];
#pragma unroll
                for (int j = 0; j < 4; j++)
                    *reinterpret_cast<uint2*>(dk + 2 * j) =
                        make_uint2(u4h2(kv[2 * i], j), u4h2(kv[2 * i + 1], j));
            }
        } else {
#pragma unroll
            for (int e = 0; e < 8; e++)
                *reinterpret_cast<uint2*>(&Vs[(8 * v_d8 + e) * ALDA + v_cb]) =
                    make_uint2(hh2u(u4h(kv[0], e), u4h(kv[1], e)),
                               hh2u(u4h(kv[2], e), u4h(kv[3], e)));
        }
    };

    float m_[2], l_[2], o[8][4];
    m_[0] = m_[1] = -CUDART_INF_F;
    l_[0] = l_[1] = 0.f;
#pragma unroll
    for (int nf = 0; nf < 8; nf++)
#pragma unroll
        for (int r = 0; r < 4; r++) o[nf][r] = 0.f;

    const int mrow = wid * 16 + lrow;
    const float LSCALE = 0.125f * 1.44269504088896341f;   // log2(e)/8

    constexpr int NT = NS / 64;   // 16 tiles
    load_kv(0);
    store_kv();
    __syncthreads();

    for (int t = 0; t < NT; t++) {
        // issue next tile's global loads early; latency hidden by compute below
        if (t + 1 < NT) load_kv((t + 1) << 6);

        // --- S = Q @ K^T ---
        float s[8][4];
#pragma unroll
        for (int nf = 0; nf < 8; nf++)
#pragma unroll
            for (int r = 0; r < 4; r++) s[nf][r] = 0.f;

#pragma unroll
        for (int kb = 0; kb < 4; kb++) {
            const int col = 8 * kb + 2 * lcol;
            const uint2 p0 = *reinterpret_cast<const uint2*>(&Qs[mrow * ALDA + col]);
            const uint2 p1 = *reinterpret_cast<const uint2*>(&Qs[(mrow + 8) * ALDA + col]);
#pragma unroll
            for (int nf = 0; nf < 8; nf++) {
                const uint2 q = *reinterpret_cast<const uint2*>(
                    &Ks[(nf * 8 + lrow) * ALDA + col]);
                mma16(s[nf], p0.x, p1.x, p0.y, p1.y, q.x, q.y);
            }
        }

        // --- online softmax (exp2 domain) ---
#pragma unroll
        for (int hh = 0; hh < 2; hh++) {
            float rm = -CUDART_INF_F;
#pragma unroll
            for (int nf = 0; nf < 8; nf++) {
                s[nf][2 * hh + 0] *= LSCALE;
                s[nf][2 * hh + 1] *= LSCALE;
                rm = fmaxf(rm, fmaxf(s[nf][2 * hh + 0], s[nf][2 * hh + 1]));
            }
            rm = fmaxf(rm, __shfl_xor_sync(0xffffffffu, rm, 1));
            rm = fmaxf(rm, __shfl_xor_sync(0xffffffffu, rm, 2));

            const float mnew  = fmaxf(m_[hh], rm);
            const float alpha = ex2(m_[hh] - mnew);
            float ps = 0.f;
#pragma unroll
            for (int nf = 0; nf < 8; nf++) {
                s[nf][2 * hh + 0] = ex2(s[nf][2 * hh + 0] - mnew);
                s[nf][2 * hh + 1] = ex2(s[nf][2 * hh + 1] - mnew);
                ps += s[nf][2 * hh + 0] + s[nf][2 * hh + 1];
            }
            ps += __shfl_xor_sync(0xffffffffu, ps, 1);
            ps += __shfl_xor_sync(0xffffffffu, ps, 2);

            l_[hh] = l_[hh] * alpha + ps;
            m_[hh] = mnew;
#pragma unroll
            for (int nf = 0; nf < 8; nf++) {
                o[nf][2 * hh + 0] *= alpha;
                o[nf][2 * hh + 1] *= alpha;
            }
        }

        // --- O += P @ V, P taken directly from S fragments ---
#pragma unroll
        for (int g = 0; g < 4; g++) {
            const uint32_t a0 = h2pack(s[2 * g][0],     s[2 * g][1]);
            const uint32_t a1 = h2pack(s[2 * g][2],     s[2 * g][3]);
            const uint32_t a2 = h2pack(s[2 * g + 1][0], s[2 * g + 1][1]);
            const uint32_t a3 = h2pack(s[2 * g + 1][2], s[2 * g + 1][3]);
            const int col = 8 * g + 2 * lcol;
#pragma unroll
            for (int nf = 0; nf < 8; nf++) {
                const int cb = col ^ (2 * (nf & 7));
                const uint2 q = *reinterpret_cast<const uint2*>(
                    &Vs[(nf * 8 + lrow) * ALDA + cb]);
                mma16(o[nf], a0, a1, a2, a3, q.x, q.y);
            }
        }

        // hand the single smem buffer to the next tile
        __syncthreads();
        if (t + 1 < NT) {
            store_kv();
            __syncthreads();
        }
    }

    // Epilogue: x[b, s, h*64+d] = o / l  (half2 stores)
    const int b = bh >> 3, h = bh & 7;
#pragma unroll
    for (int hh = 0; hh < 2; hh++) {
        const int r = q0 + mrow + hh * 8;
        const float inv = 1.f / l_[hh];
#pragma unroll
        for (int nf = 0; nf < 8; nf++) {
            const int d = nf * 8 + 2 * lcol;
            *reinterpret_cast<uint32_t*>(
                &x[((size_t)(b * NS + r)) * NF + h * NDK + d]) =
                h2pack(o[nf][2 * hh + 0] * inv, o[nf][2 * hh + 1] * inv);
        }
    }
}

// ---------------------------------------------------------------------------
extern "C" void kernel_launch(void* const* d_in, const int* in_sizes, int n_in,
                              void* d_out, int out_size)
{
    const float* query = (const float*)d_in[0];
    // d_in[1] = key_t (unused by the synthesizer module)
    const float* value = (const float*)d_in[2];
    const float* w1 = (const float*)d_in[3];
    const float* b1 = (const float*)d_in[4];
    const float* w2 = (const float*)d_in[5];
    const float* b2 = (const float*)d_in[6];
    const float* wv = (const float*)d_in[7];
    const float* bv = (const float*)d_in[8];
    const float* wo = (const float*)d_in[9];
    const float* bo = (const float*)d_in[10];
    float* out = (float*)d_out;

    __half *qh, *valh, *w1h, *w2h, *wvh, *woh, *hh, *awh, *vh, *xh;
    cudaGetSymbolAddress((void**)&qh,   g_qh);
    cudaGetSymbolAddress((void**)&valh, g_valh);
    cudaGetSymbolAddress((void**)&w1h,  g_w1h);
    cudaGetSymbolAddress((void**)&w2h,  g_w2h);
    cudaGetSymbolAddress((void**)&wvh,  g_wvh);
    cudaGetSymbolAddress((void**)&woh,  g_woh);
    cudaGetSymbolAddress((void**)&hh,   g_hh);
    cudaGetSymbolAddress((void**)&awh,  g_awh);
    cudaGetSymbolAddress((void**)&vh,   g_vh);
    cudaGetSymbolAddress((void**)&xh,   g_xh);

    const dim3 blk(256);
    const int gemm_smem = 2 * 2 * 128 * GLDAH * 4;            // 49,152 B
    const int attn_smem = (128 + 64 + 64) * ALDA * 4;         // 40,960 B
    cudaFuncSetAttribute(hgemm<0>, cudaFuncAttributeMaxDynamicSharedMemorySize, gemm_smem);
    cudaFuncSetAttribute(hgemm<1>, cudaFuncAttributeMaxDynamicSharedMemorySize, gemm_smem);
    cudaFuncSetAttribute(hgemm<2>, cudaFuncAttributeMaxDynamicSharedMemorySize, gemm_smem);
    cudaFuncSetAttribute(attn_hmma, cudaFuncAttributeMaxDynamicSharedMemorySize, attn_smem);

    // 0) fp32 -> fp16 conversions
    f2h_kernel<<<(NM * NF) / 1024, blk>>>(query, qh, NM * NF);
    f2h_kernel<<<(NM * NF) / 1024, blk>>>(value, valh, NM * NF);
    f2h_kernel<<<(NF * NHID) / 1024, blk>>>(w1, w1h, NF * NHID);
    f2h_kernel<<<(NHID * NF) / 1024, blk>>>(w2, w2h, NHID * NF);
    f2h_kernel<<<(NF * NF) / 1024, blk>>>(wv, wvh, NF * NF);
    f2h_kernel<<<(NF * NF) / 1024, blk>>>(wo, woh, NF * NF);

    // 1) h = relu(q @ w1 + b1) -> half
    hgemm<0><<<dim3(NHID / 128, NM / 128), blk, gemm_smem>>>(NM, NHID, NF, qh, w1h, b1, hh);
    // 2) aw = h @ w2 + b2 -> half [B,H,S,dk]
    hgemm<1><<<dim3(NF / 128, NM / 128), blk, gemm_smem>>>(NM, NF, NHID, hh, w2h, b2, awh);
    // 3) v = value @ wv + bv -> half [B,H,S,dk]
    hgemm<1><<<dim3(NF / 128, NM / 128), blk, gemm_smem>>>(NM, NF, NF, valh, wvh, bv, vh);
    // 4) fp16 flash attention -> half x [B,S,F]
    attn_hmma<<<dim3(NS / 128, NB * NH), blk, attn_smem>>>(awh, vh, xh);
    // 5) out = x @ wo + bo -> float
    hgemm<2><<<dim3(NF / 128, NM / 128), blk, gemm_smem>>>(NM, NF, NF, xh, woh, bo, out);
}

// round 15
// speedup vs baseline: 5.2686x; 1.0001x over previous
#include <cuda_runtime.h>
#include <cuda_fp16.h>
#include <math_constants.h>
#include <cstdint>

// Problem constants
#define NB    8
#define NS    1024
#define NF    512
#define NHID  1024
#define NH    8
#define NDK   64
#define NM    (NB * NS)        // 8192 token rows

// Scratch (allocation-free: __device__ globals), fp16 pipeline
__device__ __half g_qh  [NM * NF];           // query fp16
__device__ __half g_valh[NM * NF];           // value fp16
__device__ __half g_w1h [NF * NHID];
__device__ __half g_w2h [NHID * NF];
__device__ __half g_wvh [NF * NF];
__device__ __half g_woh [NF * NF];
__device__ __half g_hh  [NM * NHID];         // relu(q@w1+b1)
__device__ __half g_awh [NB * NH * NS * NDK];// [B,H,S,dk]
__device__ __half g_vh  [NB * NH * NS * NDK];// [B,H,S,dk]
__device__ __half g_xh  [NM * NF];           // attention out [B,S,F]

__device__ __forceinline__ uint32_t h2pack(float a, float b) {
    __half2 h = __floats2half2_rn(a, b);
    return reinterpret_cast<uint32_t&>(h);
}
__device__ __forceinline__ uint32_t hh2u(__half a, __half b) {
    __half2 h = __halves2half2(a, b);
    return reinterpret_cast<uint32_t&>(h);
}
// e-th half / j-th half2 of a uint4 (8 halves)
__device__ __forceinline__ __half u4h(const uint4& v, int e) {
    return reinterpret_cast<const __half*>(&v)[e];
}
__device__ __forceinline__ uint32_t u4h2(const uint4& v, int j) {
    return reinterpret_cast<const uint32_t*>(&v)[j];
}
__device__ __forceinline__ float ex2(float x) {
    float y;
    asm("ex2.approx.f32 %0, %1;" : "=f"(y) : "f"(x));
    return y;
}

__device__ __forceinline__ void mma16(float* c,
                                      uint32_t a0, uint32_t a1, uint32_t a2, uint32_t a3,
                                      uint32_t b0, uint32_t b1) {
    asm volatile(
        "mma.sync.aligned.m16n8k16.row.col.f32.f16.f16.f32 "
        "{%0,%1,%2,%3}, {%4,%5,%6,%7}, {%8,%9}, {%0,%1,%2,%3};"
        : "+f"(c[0]), "+f"(c[1]), "+f"(c[2]), "+f"(c[3])
        : "r"(a0), "r"(a1), "r"(a2), "r"(a3), "r"(b0), "r"(b1));
}

// ---------------------------------------------------------------------------
// fp32 -> fp16 conversion (n % 4 == 0)
// ---------------------------------------------------------------------------
__global__ void __launch_bounds__(256)
f2h_kernel(const float* __restrict__ src, __half* __restrict__ dst, int n)
{
    const int i = (blockIdx.x * 256 + threadIdx.x) * 4;
    if (i < n) {
        const float4 v = *reinterpret_cast<const float4*>(src + i);
        *reinterpret_cast<uint2*>(dst + i) =
            make_uint2(h2pack(v.x, v.y), h2pack(v.z, v.w));
    }
}

// ---------------------------------------------------------------------------
// FP16-in GEMM, double-buffered + register prefetch.
// R15: balanced stagers (low 128 thr: A only; high 128 thr: B only) to cut
// peak prefetch registers, and __launch_bounds__(256,2) to force 2 CTAs/SM.
// Mainloop fragment code byte-identical to the validated R11/R14 version.
// ---------------------------------------------------------------------------
#define GLDAH 24

template <int MODE>
__global__ void __launch_bounds__(256, 2)
hgemm(int M, int N, int K,
      const __half* __restrict__ A,
      const __half* __restrict__ W,
      const float* __restrict__ bias,
      void* __restrict__ outv)
{
    extern __shared__ uint32_t sg[];
    uint32_t (*As2)[GLDAH] = reinterpret_cast<uint32_t(*)[GLDAH]>(sg);
    uint32_t (*Bs2)[GLDAH] = reinterpret_cast<uint32_t(*)[GLDAH]>(sg + 2 * 128 * GLDAH);

    const int tid  = threadIdx.x;
    const int bm   = blockIdx.y * 128;
    const int bn   = blockIdx.x * 128;
    const int wid  = tid >> 5;
    const int lane = tid & 31;
    const int wr   = wid & 1;
    const int wc   = wid >> 1;
    const int lrow = lane >> 2;
    const int lcol = lane & 3;

    // B stager constants (high 128 threads): t2 = tid-128
    const int t2   = tid - 128;
    const int b_n8 = t2 & 15;
    const int b_kq = t2 >> 4;
    const int b_p  = ((b_kq >> 2) << 3) + (b_kq & 3);
    const int b_cb = ((b_p & ~7) + 2 * (b_p & 3)) ^ (2 * (b_n8 & 7));

    uint4 pf[4];   // prefetch: A row (4 seg-quads) OR B (4 row-quads)

    auto load_tiles = [&](int k0) {
        if (tid < 128) {
            const __half* p = &A[(size_t)(bm + tid) * K + k0];
            pf[0] = *reinterpret_cast<const uint4*>(p);
            pf[1] = *reinterpret_cast<const uint4*>(p + 8);
            pf[2] = *reinterpret_cast<const uint4*>(p + 16);
            pf[3] = *reinterpret_cast<const uint4*>(p + 24);
        } else {
            const __half* q = &W[(size_t)(k0 + 2 * b_p) * N + bn + 8 * b_n8];
            pf[0] = *reinterpret_cast<const uint4*>(q);
            pf[1] = *reinterpret_cast<const uint4*>(q + (size_t)N);
            pf[2] = *reinterpret_cast<const uint4*>(q + (size_t)8 * N);
            pf[3] = *reinterpret_cast<const uint4*>(q + (size_t)9 * N);
        }
    };
    auto store_tiles = [&](int buf) {
        if (tid < 128) {
            uint32_t* da = &As2[buf * 128 + tid][0];
#pragma unroll
            for (int j = 0; j < 4; j++) {
                *reinterpret_cast<uint2*>(da + 2 * j) =
                    make_uint2(u4h2(pf[0], j), u4h2(pf[1], j));     // pairs (j, j+4)
                *reinterpret_cast<uint2*>(da + 8 + 2 * j) =
                    make_uint2(u4h2(pf[2], j), u4h2(pf[3], j));     // pairs (8+j, 12+j)
            }
        } else {
#pragma unroll
            for (int e = 0; e < 8; e++)
                *reinterpret_cast<uint2*>(&Bs2[buf * 128 + 8 * b_n8 + e][b_cb]) =
                    make_uint2(hh2u(u4h(pf[0], e), u4h(pf[1], e)),
                               hh2u(u4h(pf[2], e), u4h(pf[3], e)));
        }
    };

    float c[4][4][4];
#pragma unroll
    for (int mf = 0; mf < 4; mf++)
#pragma unroll
        for (int nf = 0; nf < 4; nf++)
#pragma unroll
            for (int r = 0; r < 4; r++) c[mf][nf][r] = 0.f;

    const int T = K >> 5;
    load_tiles(0);
    store_tiles(0);
    load_tiles(32);
    __syncthreads();

    int cur = 0;
    for (int t = 0; t < T; t++) {
        if (t + 1 < T) {
            store_tiles(cur ^ 1);
            if (t + 2 < T) load_tiles((t + 2) << 5);
        }
#pragma unroll
        for (int kb = 0; kb < 2; kb++) {
            const int col = 8 * kb + 2 * lcol;
            uint32_t af[4][4];
#pragma unroll
            for (int mf = 0; mf < 4; mf++) {
                const int m = cur * 128 + wr * 64 + mf * 16 + lrow;
                const uint2 p0 = *reinterpret_cast<const uint2*>(&As2[m][col]);
                const uint2 p1 = *reinterpret_cast<const uint2*>(&As2[m + 8][col]);
                af[mf][0] = p0.x; af[mf][2] = p0.y;
                af[mf][1] = p1.x; af[mf][3] = p1.y;
            }
            uint32_t bf[4][2];
#pragma unroll
            for (int nf = 0; nf < 4; nf++) {
                const int nl = wc * 32 + nf * 8 + lrow;
                const int cb = col ^ (2 * ((wc * 4 + nf) & 7));
                const uint2 q = *reinterpret_cast<const uint2*>(&Bs2[cur * 128 + nl][cb]);
                bf[nf][0] = q.x; bf[nf][1] = q.y;
            }
#pragma unroll
            for (int mf = 0; mf < 4; mf++)
#pragma unroll
                for (int nf = 0; nf < 4; nf++)
                    mma16(c[mf][nf], af[mf][0], af[mf][1], af[mf][2], af[mf][3],
                          bf[nf][0], bf[nf][1]);
        }
        __syncthreads();
        cur ^= 1;
    }

#pragma unroll
    for (int mf = 0; mf < 4; mf++) {
#pragma unroll
        for (int nf = 0; nf < 4; nf++) {
            const int row0 = bm + wr * 64 + mf * 16 + lrow;
            const int col0 = bn + wc * 32 + nf * 8 + 2 * lcol;
            const float bsum0 = bias[col0], bsum1 = bias[col0 + 1];
#pragma unroll
            for (int half = 0; half < 2; half++) {
                const int m = row0 + half * 8;
                float v0 = c[mf][nf][half * 2 + 0] + bsum0;
                float v1 = c[mf][nf][half * 2 + 1] + bsum1;
                if (MODE == 0) {
                    v0 = fmaxf(v0, 0.f); v1 = fmaxf(v1, 0.f);
                    *reinterpret_cast<uint32_t*>(
                        &((__half*)outv)[(size_t)m * N + col0]) = h2pack(v0, v1);
                } else if (MODE == 1) {
                    const int b = m >> 10, s = m & 1023;
                    const int h = col0 >> 6, d = col0 & 63;
                    *reinterpret_cast<uint32_t*>(
                        &((__half*)outv)[((((size_t)b * NH + h) * NS + s) * NDK) + d]) =
                        h2pack(v0, v1);
                } else {
                    *reinterpret_cast<float2*>(
                        &((float*)outv)[(size_t)m * N + col0]) = make_float2(v0, v1);
                }
            }
        }
    }
}

// ---------------------------------------------------------------------------
// FP16 flash attention (unchanged from passing R14 kernel).
// ---------------------------------------------------------------------------
#define ALDA 40

__global__ void __launch_bounds__(256, 2)
attn_hmma(const __half* __restrict__ aw,
          const __half* __restrict__ vv,
          __half* __restrict__ x)
{
    extern __shared__ uint32_t smu[];
    uint32_t* Qs = smu;                // [128][40]  [q][csw(d2)]
    uint32_t* Ks = Qs + 128 * ALDA;    // [64][40]   [key][csw(d2)]
    uint32_t* Vs = Ks + 64 * ALDA;     // [64][40]   [d][csw(key2)^swz]

    const int tid  = threadIdx.x;
    const int wid  = tid >> 5;
    const int lane = tid & 31;
    const int lrow = lane >> 2;
    const int lcol = lane & 3;
    const int bh   = blockIdx.y;
    const int q0   = blockIdx.x * 128;

    const __half* Abh = aw + (size_t)bh * NS * NDK;
    const __half* Vbh = vv + (size_t)bh * NS * NDK;

    // Q stager: 512 units = 128 rows x 4 segs of 16 halves
#pragma unroll
    for (int i = 0; i < 2; i++) {
        const int u = tid + i * 256;
        const int r = u >> 2, s = u & 3;
        const __half* p = &Abh[(size_t)(q0 + r) * NDK + 16 * s];
        const uint4 ua = *reinterpret_cast<const uint4*>(p);
        const uint4 ub = *reinterpret_cast<const uint4*>(p + 8);
        uint32_t* dq = &Qs[r * ALDA + 8 * s];
#pragma unroll
        for (int j = 0; j < 4; j++)
            *reinterpret_cast<uint2*>(dq + 2 * j) =
                make_uint2(u4h2(ua, j), u4h2(ub, j));
    }

    // V stager constants (threads 128..255)
    const int v_t2 = tid - 128;
    const int v_d8 = v_t2 & 7;
    const int v_pq = v_t2 >> 3;
    const int v_p  = ((v_pq >> 2) << 3) + (v_pq & 3);
    const int v_cb = ((v_p & ~7) + 2 * (v_p & 3)) ^ (2 * (v_d8 & 7));

    uint4 kv[4];
    auto load_kv = [&](int k0) {
        if (tid < 128) {
#pragma unroll
            for (int i = 0; i < 2; i++) {
                const int u = tid + i * 128;
                const int r = u >> 2, s = u & 3;
                const __half* p = &Abh[(size_t)(k0 + r) * NDK + 16 * s];
                kv[2 * i]     = *reinterpret_cast<const uint4*>(p);
                kv[2 * i + 1] = *reinterpret_cast<const uint4*>(p + 8);
            }
        } else {
            const __half* q = &Vbh[(size_t)(k0 + 2 * v_p) * NDK + 8 * v_d8];
            kv[0] = *reinterpret_cast<const uint4*>(q);
            kv[1] = *reinterpret_cast<const uint4*>(q + (size_t)NDK);
            kv[2] = *reinterpret_cast<const uint4*>(q + (size_t)8 * NDK);
            kv[3] = *reinterpret_cast<const uint4*>(q + (size_t)9 * NDK);
        }
    };
    auto store_kv = [&]() {
        if (tid < 128) {
#pragma unroll
            for (int i = 0; i < 2; i++) {
                const int u = tid + i * 128;
                const int r = u >> 2, s = u & 3;
                uint32_t* dk = &Ks[r * ALDA + 8 * s];
#pragma unroll
                for (int j = 0; j < 4; j++)
                    *reinterpret_cast<uint2*>(dk + 2 * j) =
                        make_uint2(u4h2(kv[2 * i], j), u4h2(kv[2 * i + 1], j));
            }
        } else {
#pragma unroll
            for (int e = 0; e < 8; e++)
                *reinterpret_cast<uint2*>(&Vs[(8 * v_d8 + e) * ALDA + v_cb]) =
                    make_uint2(hh2u(u4h(kv[0], e), u4h(kv[1], e)),
                               hh2u(u4h(kv[2], e), u4h(kv[3], e)));
        }
    };

    float m_[2], l_[2], o[8][4];
    m_[0] = m_[1] = -CUDART_INF_F;
    l_[0] = l_[1] = 0.f;
#pragma unroll
    for (int nf = 0; nf < 8; nf++)
#pragma unroll
        for (int r = 0; r < 4; r++) o[nf][r] = 0.f;

    const int mrow = wid * 16 + lrow;
    const float LSCALE = 0.125f * 1.44269504088896341f;   // log2(e)/8

    constexpr int NT = NS / 64;   // 16 tiles
    load_kv(0);
    store_kv();
    __syncthreads();

    for (int t = 0; t < NT; t++) {
        if (t + 1 < NT) load_kv((t + 1) << 6);

        // --- S = Q @ K^T ---
        float s[8][4];
#pragma unroll
        for (int nf = 0; nf < 8; nf++)
#pragma unroll
            for (int r = 0; r < 4; r++) s[nf][r] = 0.f;

#pragma unroll
        for (int kb = 0; kb < 4; kb++) {
            const int col = 8 * kb + 2 * lcol;
            const uint2 p0 = *reinterpret_cast<const uint2*>(&Qs[mrow * ALDA + col]);
            const uint2 p1 = *reinterpret_cast<const uint2*>(&Qs[(mrow + 8) * ALDA + col]);
#pragma unroll
            for (int nf = 0; nf < 8; nf++) {
                const uint2 q = *reinterpret_cast<const uint2*>(
                    &Ks[(nf * 8 + lrow) * ALDA + col]);
                mma16(s[nf], p0.x, p1.x, p0.y, p1.y, q.x, q.y);
            }
        }

        // --- online softmax (exp2 domain) ---
#pragma unroll
        for (int hh = 0; hh < 2; hh++) {
            float rm = -CUDART_INF_F;
#pragma unroll
            for (int nf = 0; nf < 8; nf++) {
                s[nf][2 * hh + 0] *= LSCALE;
                s[nf][2 * hh + 1] *= LSCALE;
                rm = fmaxf(rm, fmaxf(s[nf][2 * hh + 0], s[nf][2 * hh + 1]));
            }
            rm = fmaxf(rm, __shfl_xor_sync(0xffffffffu, rm, 1));
            rm = fmaxf(rm, __shfl_xor_sync(0xffffffffu, rm, 2));

            const float mnew  = fmaxf(m_[hh], rm);
            const float alpha = ex2(m_[hh] - mnew);
            float ps = 0.f;
#pragma unroll
            for (int nf = 0; nf < 8; nf++) {
                s[nf][2 * hh + 0] = ex2(s[nf][2 * hh + 0] - mnew);
                s[nf][2 * hh + 1] = ex2(s[nf][2 * hh + 1] - mnew);
                ps += s[nf][2 * hh + 0] + s[nf][2 * hh + 1];
            }
            ps += __shfl_xor_sync(0xffffffffu, ps, 1);
            ps += __shfl_xor_sync(0xffffffffu, ps, 2);

            l_[hh] = l_[hh] * alpha + ps;
            m_[hh] = mnew;
#pragma unroll
            for (int nf = 0; nf < 8; nf++) {
                o[nf][2 * hh + 0] *= alpha;
                o[nf][2 * hh + 1] *= alpha;
            }
        }

        // --- O += P @ V, P taken directly from S fragments ---
#pragma unroll
        for (int g = 0; g < 4; g++) {
            const uint32_t a0 = h2pack(s[2 * g][0],     s[2 * g][1]);
            const uint32_t a1 = h2pack(s[2 * g][2],     s[2 * g][3]);
            const uint32_t a2 = h2pack(s[2 * g + 1][0], s[2 * g + 1][1]);
            const uint32_t a3 = h2pack(s[2 * g + 1][2], s[2 * g + 1][3]);
            const int col = 8 * g + 2 * lcol;
#pragma unroll
            for (int nf = 0; nf < 8; nf++) {
                const int cb = col ^ (2 * (nf & 7));
                const uint2 q = *reinterpret_cast<const uint2*>(
                    &Vs[(nf * 8 + lrow) * ALDA + cb]);
                mma16(o[nf], a0, a1, a2, a3, q.x, q.y);
            }
        }

        __syncthreads();
        if (t + 1 < NT) {
            store_kv();
            __syncthreads();
        }
    }

    // Epilogue: x[b, s, h*64+d] = o / l  (half2 stores)
    const int b = bh >> 3, h = bh & 7;
#pragma unroll
    for (int hh = 0; hh < 2; hh++) {
        const int r = q0 + mrow + hh * 8;
        const float inv = 1.f / l_[hh];
#pragma unroll
        for (int nf = 0; nf < 8; nf++) {
            const int d = nf * 8 + 2 * lcol;
            *reinterpret_cast<uint32_t*>(
                &x[((size_t)(b * NS + r)) * NF + h * NDK + d]) =
                h2pack(o[nf][2 * hh + 0] * inv, o[nf][2 * hh + 1] * inv);
        }
    }
}

// ---------------------------------------------------------------------------
extern "C" void kernel_launch(void* const* d_in, const int* in_sizes, int n_in,
                              void* d_out, int out_size)
{
    const float* query = (const float*)d_in[0];
    // d_in[1] = key_t (unused by the synthesizer module)
    const float* value = (const float*)d_in[2];
    const float* w1 = (const float*)d_in[3];
    const float* b1 = (const float*)d_in[4];
    const float* w2 = (const float*)d_in[5];
    const float* b2 = (const float*)d_in[6];
    const float* wv = (const float*)d_in[7];
    const float* bv = (const float*)d_in[8];
    const float* wo = (const float*)d_in[9];
    const float* bo = (const float*)d_in[10];
    float* out = (float*)d_out;

    __half *qh, *valh, *w1h, *w2h, *wvh, *woh, *hh, *awh, *vh, *xh;
    cudaGetSymbolAddress((void**)&qh,   g_qh);
    cudaGetSymbolAddress((void**)&valh, g_valh);
    cudaGetSymbolAddress((void**)&w1h,  g_w1h);
    cudaGetSymbolAddress((void**)&w2h,  g_w2h);
    cudaGetSymbolAddress((void**)&wvh,  g_wvh);
    cudaGetSymbolAddress((void**)&woh,  g_woh);
    cudaGetSymbolAddress((void**)&hh,   g_hh);
    cudaGetSymbolAddress((void**)&awh,  g_awh);
    cudaGetSymbolAddress((void**)&vh,   g_vh);
    cudaGetSymbolAddress((void**)&xh,   g_xh);

    const dim3 blk(256);
    const int gemm_smem = 2 * 2 * 128 * GLDAH * 4;            // 49,152 B
    const int attn_smem = (128 + 64 + 64) * ALDA * 4;         // 40,960 B
    cudaFuncSetAttribute(hgemm<0>, cudaFuncAttributeMaxDynamicSharedMemorySize, gemm_smem);
    cudaFuncSetAttribute(hgemm<1>, cudaFuncAttributeMaxDynamicSharedMemorySize, gemm_smem);
    cudaFuncSetAttribute(hgemm<2>, cudaFuncAttributeMaxDynamicSharedMemorySize, gemm_smem);
    cudaFuncSetAttribute(attn_hmma, cudaFuncAttributeMaxDynamicSharedMemorySize, attn_smem);

    // 0) fp32 -> fp16 conversions
    f2h_kernel<<<(NM * NF) / 1024, blk>>>(query, qh, NM * NF);
    f2h_kernel<<<(NM * NF) / 1024, blk>>>(value, valh, NM * NF);
    f2h_kernel<<<(NF * NHID) / 1024, blk>>>(w1, w1h, NF * NHID);
    f2h_kernel<<<(NHID * NF) / 1024, blk>>>(w2, w2h, NHID * NF);
    f2h_kernel<<<(NF * NF) / 1024, blk>>>(wv, wvh, NF * NF);
    f2h_kernel<<<(NF * NF) / 1024, blk>>>(wo, woh, NF * NF);

    // 1) h = relu(q @ w1 + b1) -> half
    hgemm<0><<<dim3(NHID / 128, NM / 128), blk, gemm_smem>>>(NM, NHID, NF, qh, w1h, b1, hh);
    // 2) aw = h @ w2 + b2 -> half [B,H,S,dk]
    hgemm<1><<<dim3(NF / 128, NM / 128), blk, gemm_smem>>>(NM, NF, NHID, hh, w2h, b2, awh);
    // 3) v = value @ wv + bv -> half [B,H,S,dk]
    hgemm<1><<<dim3(NF / 128, NM / 128), blk, gemm_smem>>>(NM, NF, NF, valh, wvh, bv, vh);
    // 4) fp16 flash attention -> half x [B,S,F]
    attn_hmma<<<dim3(NS / 128, NB * NH), blk, attn_smem>>>(awh, vh, xh);
    // 5) out = x @ wo + bo -> float
    hgemm<2><<<dim3(NF / 128, NM / 128), blk, gemm_smem>>>(NM, NF, NF, xh, woh, bo, out);
}

// round 17
// speedup vs baseline: 5.4763x; 1.0394x over previous
#include <cuda_runtime.h>
#include <cuda_fp16.h>
#include <math_constants.h>
#include <cstdint>

// Problem constants
#define NB    8
#define NS    1024
#define NF    512
#define NHID  1024
#define NH    8
#define NDK   64
#define NM    (NB * NS)        // 8192 token rows

// Scratch (allocation-free: __device__ globals), fp16 pipeline
__device__ __half g_qh  [NM * NF];           // query fp16
__device__ __half g_valh[NM * NF];           // value fp16
__device__ __half g_w1h [NF * NHID];
__device__ __half g_w2h [NHID * NF];
__device__ __half g_wvh [NF * NF];
__device__ __half g_woh [NF * NF];
__device__ __half g_hh  [NM * NHID];         // relu(q@w1+b1)
__device__ __half g_awh [NB * NH * NS * NDK];// [B,H,S,dk]
__device__ __half g_vh  [NB * NH * NS * NDK];// [B,H,S,dk]
__device__ __half g_xh  [NM * NF];           // attention out [B,S,F]

__device__ __forceinline__ uint32_t h2pack(float a, float b) {
    __half2 h = __floats2half2_rn(a, b);
    return reinterpret_cast<uint32_t&>(h);
}
__device__ __forceinline__ uint32_t hh2u(__half a, __half b) {
    __half2 h = __halves2half2(a, b);
    return reinterpret_cast<uint32_t&>(h);
}
// e-th half / j-th half2 of a uint4 (8 halves)
__device__ __forceinline__ __half u4h(const uint4& v, int e) {
    return reinterpret_cast<const __half*>(&v)[e];
}
__device__ __forceinline__ uint32_t u4h2(const uint4& v, int j) {
    return reinterpret_cast<const uint32_t*>(&v)[j];
}
__device__ __forceinline__ float ex2(float x) {
    float y;
    asm("ex2.approx.f32 %0, %1;" : "=f"(y) : "f"(x));
    return y;
}

__device__ __forceinline__ void mma16(float* c,
                                      uint32_t a0, uint32_t a1, uint32_t a2, uint32_t a3,
                                      uint32_t b0, uint32_t b1) {
    asm volatile(
        "mma.sync.aligned.m16n8k16.row.col.f32.f16.f16.f32 "
        "{%0,%1,%2,%3}, {%4,%5,%6,%7}, {%8,%9}, {%0,%1,%2,%3};"
        : "+f"(c[0]), "+f"(c[1]), "+f"(c[2]), "+f"(c[3])
        : "r"(a0), "r"(a1), "r"(a2), "r"(a3), "r"(b0), "r"(b1));
}

// ---------------------------------------------------------------------------
// Batched fp32 -> fp16 conversion: all six tensors in one launch.
// Block ranges (1024 elems per block):
//   q:     [0, 4096)     value: [4096, 8192)
//   w1:    [8192, 8704)  w2:    [8704, 9216)
//   wv:    [9216, 9472)  wo:    [9472, 9728)
// ---------------------------------------------------------------------------
__global__ void __launch_bounds__(256)
f2h_batch(const float* __restrict__ s0, __half* __restrict__ d0,
          const float* __restrict__ s1, __half* __restrict__ d1,
          const float* __restrict__ s2, __half* __restrict__ d2,
          const float* __restrict__ s3, __half* __restrict__ d3,
          const float* __restrict__ s4, __half* __restrict__ d4,
          const float* __restrict__ s5, __half* __restrict__ d5)
{
    const int b = blockIdx.x;
    const float* s;
    __half* d;
    int off;
    if (b < 4096)      { s = s0; d = d0; off = b; }
    else if (b < 8192) { s = s1; d = d1; off = b - 4096; }
    else if (b < 8704) { s = s2; d = d2; off = b - 8192; }
    else if (b < 9216) { s = s3; d = d3; off = b - 8704; }
    else if (b < 9472) { s = s4; d = d4; off = b - 9216; }
    else               { s = s5; d = d5; off = b - 9472; }
    const int i = (off * 256 + threadIdx.x) * 4;
    const float4 v = *reinterpret_cast<const float4*>(s + i);
    *reinterpret_cast<uint2*>(d + i) =
        make_uint2(h2pack(v.x, v.y), h2pack(v.z, v.w));
}

// ---------------------------------------------------------------------------
// FP16-in GEMM, double-buffered + register prefetch (unchanged from R15 pass).
// ---------------------------------------------------------------------------
#define GLDAH 24

template <int MODE>
__global__ void __launch_bounds__(256, 2)
hgemm(int M, int N, int K,
      const __half* __restrict__ A,
      const __half* __restrict__ W,
      const float* __restrict__ bias,
      void* __restrict__ outv)
{
    extern __shared__ uint32_t sg[];
    uint32_t (*As2)[GLDAH] = reinterpret_cast<uint32_t(*)[GLDAH]>(sg);
    uint32_t (*Bs2)[GLDAH] = reinterpret_cast<uint32_t(*)[GLDAH]>(sg + 2 * 128 * GLDAH);

    const int tid  = threadIdx.x;
    const int bm   = blockIdx.y * 128;
    const int bn   = blockIdx.x * 128;
    const int wid  = tid >> 5;
    const int lane = tid & 31;
    const int wr   = wid & 1;
    const int wc   = wid >> 1;
    const int lrow = lane >> 2;
    const int lcol = lane & 3;

    // B stager constants (high 128 threads): t2 = tid-128
    const int t2   = tid - 128;
    const int b_n8 = t2 & 15;
    const int b_kq = t2 >> 4;
    const int b_p  = ((b_kq >> 2) << 3) + (b_kq & 3);
    const int b_cb = ((b_p & ~7) + 2 * (b_p & 3)) ^ (2 * (b_n8 & 7));

    uint4 pf[4];   // prefetch: A row (4 seg-quads) OR B (4 row-quads)

    auto load_tiles = [&](int k0) {
        if (tid < 128) {
            const __half* p = &A[(size_t)(bm + tid) * K + k0];
            pf[0] = *reinterpret_cast<const uint4*>(p);
            pf[1] = *reinterpret_cast<const uint4*>(p + 8);
            pf[2] = *reinterpret_cast<const uint4*>(p + 16);
            pf[3] = *reinterpret_cast<const uint4*>(p + 24);
        } else {
            const __half* q = &W[(size_t)(k0 + 2 * b_p) * N + bn + 8 * b_n8];
            pf[0] = *reinterpret_cast<const uint4*>(q);
            pf[1] = *reinterpret_cast<const uint4*>(q + (size_t)N);
            pf[2] = *reinterpret_cast<const uint4*>(q + (size_t)8 * N);
            pf[3] = *reinterpret_cast<const uint4*>(q + (size_t)9 * N);
        }
    };
    auto store_tiles = [&](int buf) {
        if (tid < 128) {
            uint32_t* da = &As2[buf * 128 + tid][0];
#pragma unroll
            for (int j = 0; j < 4; j++) {
                *reinterpret_cast<uint2*>(da + 2 * j) =
                    make_uint2(u4h2(pf[0], j), u4h2(pf[1], j));     // pairs (j, j+4)
                *reinterpret_cast<uint2*>(da + 8 + 2 * j) =
                    make_uint2(u4h2(pf[2], j), u4h2(pf[3], j));     // pairs (8+j, 12+j)
            }
        } else {
#pragma unroll
            for (int e = 0; e < 8; e++)
                *reinterpret_cast<uint2*>(&Bs2[buf * 128 + 8 * b_n8 + e][b_cb]) =
                    make_uint2(hh2u(u4h(pf[0], e), u4h(pf[1], e)),
                               hh2u(u4h(pf[2], e), u4h(pf[3], e)));
        }
    };

    float c[4][4][4];
#pragma unroll
    for (int mf = 0; mf < 4; mf++)
#pragma unroll
        for (int nf = 0; nf < 4; nf++)
#pragma unroll
            for (int r = 0; r < 4; r++) c[mf][nf][r] = 0.f;

    const int T = K >> 5;
    load_tiles(0);
    store_tiles(0);
    load_tiles(32);
    __syncthreads();

    int cur = 0;
    for (int t = 0; t < T; t++) {
        if (t + 1 < T) {
            store_tiles(cur ^ 1);
            if (t + 2 < T) load_tiles((t + 2) << 5);
        }
#pragma unroll
        for (int kb = 0; kb < 2; kb++) {
            const int col = 8 * kb + 2 * lcol;
            uint32_t af[4][4];
#pragma unroll
            for (int mf = 0; mf < 4; mf++) {
                const int m = cur * 128 + wr * 64 + mf * 16 + lrow;
                const uint2 p0 = *reinterpret_cast<const uint2*>(&As2[m][col]);
                const uint2 p1 = *reinterpret_cast<const uint2*>(&As2[m + 8][col]);
                af[mf][0] = p0.x; af[mf][2] = p0.y;
                af[mf][1] = p1.x; af[mf][3] = p1.y;
            }
            uint32_t bf[4][2];
#pragma unroll
            for (int nf = 0; nf < 4; nf++) {
                const int nl = wc * 32 + nf * 8 + lrow;
                const int cb = col ^ (2 * ((wc * 4 + nf) & 7));
                const uint2 q = *reinterpret_cast<const uint2*>(&Bs2[cur * 128 + nl][cb]);
                bf[nf][0] = q.x; bf[nf][1] = q.y;
            }
#pragma unroll
            for (int mf = 0; mf < 4; mf++)
#pragma unroll
                for (int nf = 0; nf < 4; nf++)
                    mma16(c[mf][nf], af[mf][0], af[mf][1], af[mf][2], af[mf][3],
                          bf[nf][0], bf[nf][1]);
        }
        __syncthreads();
        cur ^= 1;
    }

#pragma unroll
    for (int mf = 0; mf < 4; mf++) {
#pragma unroll
        for (int nf = 0; nf < 4; nf++) {
            const int row0 = bm + wr * 64 + mf * 16 + lrow;
            const int col0 = bn + wc * 32 + nf * 8 + 2 * lcol;
            const float bsum0 = bias[col0], bsum1 = bias[col0 + 1];
#pragma unroll
            for (int half = 0; half < 2; half++) {
                const int m = row0 + half * 8;
                float v0 = c[mf][nf][half * 2 + 0] + bsum0;
                float v1 = c[mf][nf][half * 2 + 1] + bsum1;
                if (MODE == 0) {
                    v0 = fmaxf(v0, 0.f); v1 = fmaxf(v1, 0.f);
                    *reinterpret_cast<uint32_t*>(
                        &((__half*)outv)[(size_t)m * N + col0]) = h2pack(v0, v1);
                } else if (MODE == 1) {
                    const int b = m >> 10, s = m & 1023;
                    const int h = col0 >> 6, d = col0 & 63;
                    *reinterpret_cast<uint32_t*>(
                        &((__half*)outv)[((((size_t)b * NH + h) * NS + s) * NDK) + d]) =
                        h2pack(v0, v1);
                } else {
                    *reinterpret_cast<float2*>(
                        &((float*)outv)[(size_t)m * N + col0]) = make_float2(v0, v1);
                }
            }
        }
    }
}

// ---------------------------------------------------------------------------
// FP16 flash attention (unchanged from passing R14/R15 kernel).
// ---------------------------------------------------------------------------
#define ALDA 40

__global__ void __launch_bounds__(256, 2)
attn_hmma(const __half* __restrict__ aw,
          const __half* __restrict__ vv,
          __half* __restrict__ x)
{
    extern __shared__ uint32_t smu[];
    uint32_t* Qs = smu;                // [128][40]  [q][csw(d2)]
    uint32_t* Ks = Qs + 128 * ALDA;    // [64][40]   [key][csw(d2)]
    uint32_t* Vs = Ks + 64 * ALDA;     // [64][40]   [d][csw(key2)^swz]

    const int tid  = threadIdx.x;
    const int wid  = tid >> 5;
    const int lane = tid & 31;
    const int lrow = lane >> 2;
    const int lcol = lane & 3;
    const int bh   = blockIdx.y;
    const int q0   = blockIdx.x * 128;

    const __half* Abh = aw + (size_t)bh * NS * NDK;
    const __half* Vbh = vv + (size_t)bh * NS * NDK;

    // Q stager: 512 units = 128 rows x 4 segs of 16 halves
#pragma unroll
    for (int i = 0; i < 2; i++) {
        const int u = tid + i * 256;
        const int r = u >> 2, s = u & 3;
        const __half* p = &Abh[(size_t)(q0 + r) * NDK + 16 * s];
        const uint4 ua = *reinterpret_cast<const uint4*>(p);
        const uint4 ub = *reinterpret_cast<const uint4*>(p + 8);
        uint32_t* dq = &Qs[r * ALDA + 8 * s];
#pragma unroll
        for (int j = 0; j < 4; j++)
            *reinterpret_cast<uint2*>(dq + 2 * j) =
                make_uint2(u4h2(ua, j), u4h2(ub, j));
    }

    // V stager constants (threads 128..255)
    const int v_t2 = tid - 128;
    const int v_d8 = v_t2 & 7;
    const int v_pq = v_t2 >> 3;
    const int v_p  = ((v_pq >> 2) << 3) + (v_pq & 3);
    const int v_cb = ((v_p & ~7) + 2 * (v_p & 3)) ^ (2 * (v_d8 & 7));

    uint4 kv[4];
    auto load_kv = [&](int k0) {
        if (tid < 128) {
#pragma unroll
            for (int i = 0; i < 2; i++) {
                const int u = tid + i * 128;
                const int r = u >> 2, s = u & 3;
                const __half* p = &Abh[(size_t)(k0 + r) * NDK + 16 * s];
                kv[2 * i]     = *reinterpret_cast<const uint4*>(p);
                kv[2 * i + 1] = *reinterpret_cast<const uint4*>(p + 8);
            }
        } else {
            const __half* q = &Vbh[(size_t)(k0 + 2 * v_p) * NDK + 8 * v_d8];
            kv[0] = *reinterpret_cast<const uint4*>(q);
            kv[1] = *reinterpret_cast<const uint4*>(q + (size_t)NDK);
            kv[2] = *reinterpret_cast<const uint4*>(q + (size_t)8 * NDK);
            kv[3] = *reinterpret_cast<const uint4*>(q + (size_t)9 * NDK);
        }
    };
    auto store_kv = [&]() {
        if (tid < 128) {
#pragma unroll
            for (int i = 0; i < 2; i++) {
                const int u = tid + i * 128;
                const int r = u >> 2, s = u & 3;
                uint32_t* dk = &Ks[r * ALDA + 8 * s];
#pragma unroll
                for (int j = 0; j < 4; j++)
                    *reinterpret_cast<uint2*>(dk + 2 * j) =
                        make_uint2(u4h2(kv[2 * i], j), u4h2(kv[2 * i + 1], j));
            }
        } else {
#pragma unroll
            for (int e = 0; e < 8; e++)
                *reinterpret_cast<uint2*>(&Vs[(8 * v_d8 + e) * ALDA + v_cb]) =
                    make_uint2(hh2u(u4h(kv[0], e), u4h(kv[1], e)),
                               hh2u(u4h(kv[2], e), u4h(kv[3], e)));
        }
    };

    float m_[2], l_[2], o[8][4];
    m_[0] = m_[1] = -CUDART_INF_F;
    l_[0] = l_[1] = 0.f;
#pragma unroll
    for (int nf = 0; nf < 8; nf++)
#pragma unroll
        for (int r = 0; r < 4; r++) o[nf][r] = 0.f;

    const int mrow = wid * 16 + lrow;
    const float LSCALE = 0.125f * 1.44269504088896341f;   // log2(e)/8

    constexpr int NT = NS / 64;   // 16 tiles
    load_kv(0);
    store_kv();
    __syncthreads();

    for (int t = 0; t < NT; t++) {
        if (t + 1 < NT) load_kv((t + 1) << 6);

        // --- S = Q @ K^T ---
        float s[8][4];
#pragma unroll
        for (int nf = 0; nf < 8; nf++)
#pragma unroll
            for (int r = 0; r < 4; r++) s[nf][r] = 0.f;

#pragma unroll
        for (int kb = 0; kb < 4; kb++) {
            const int col = 8 * kb + 2 * lcol;
            const uint2 p0 = *reinterpret_cast<const uint2*>(&Qs[mrow * ALDA + col]);
            const uint2 p1 = *reinterpret_cast<const uint2*>(&Qs[(mrow + 8) * ALDA + col]);
#pragma unroll
            for (int nf = 0; nf < 8; nf++) {
                const uint2 q = *reinterpret_cast<const uint2*>(
                    &Ks[(nf * 8 + lrow) * ALDA + col]);
                mma16(s[nf], p0.x, p1.x, p0.y, p1.y, q.x, q.y);
            }
        }

        // --- online softmax (exp2 domain) ---
#pragma unroll
        for (int hh = 0; hh < 2; hh++) {
            float rm = -CUDART_INF_F;
#pragma unroll
            for (int nf = 0; nf < 8; nf++) {
                s[nf][2 * hh + 0] *= LSCALE;
                s[nf][2 * hh + 1] *= LSCALE;
                rm = fmaxf(rm, fmaxf(s[nf][2 * hh + 0], s[nf][2 * hh + 1]));
            }
            rm = fmaxf(rm, __shfl_xor_sync(0xffffffffu, rm, 1));
            rm = fmaxf(rm, __shfl_xor_sync(0xffffffffu, rm, 2));

            const float mnew  = fmaxf(m_[hh], rm);
            const float alpha = ex2(m_[hh] - mnew);
            float ps = 0.f;
#pragma unroll
            for (int nf = 0; nf < 8; nf++) {
                s[nf][2 * hh + 0] = ex2(s[nf][2 * hh + 0] - mnew);
                s[nf][2 * hh + 1] = ex2(s[nf][2 * hh + 1] - mnew);
                ps += s[nf][2 * hh + 0] + s[nf][2 * hh + 1];
            }
            ps += __shfl_xor_sync(0xffffffffu, ps, 1);
            ps += __shfl_xor_sync(0xffffffffu, ps, 2);

            l_[hh] = l_[hh] * alpha + ps;
            m_[hh] = mnew;
#pragma unroll
            for (int nf = 0; nf < 8; nf++) {
                o[nf][2 * hh + 0] *= alpha;
                o[nf][2 * hh + 1] *= alpha;
            }
        }

        // --- O += P @ V, P taken directly from S fragments ---
#pragma unroll
        for (int g = 0; g < 4; g++) {
            const uint32_t a0 = h2pack(s[2 * g][0],     s[2 * g][1]);
            const uint32_t a1 = h2pack(s[2 * g][2],     s[2 * g][3]);
            const uint32_t a2 = h2pack(s[2 * g + 1][0], s[2 * g + 1][1]);
            const uint32_t a3 = h2pack(s[2 * g + 1][2], s[2 * g + 1][3]);
            const int col = 8 * g + 2 * lcol;
#pragma unroll
            for (int nf = 0; nf < 8; nf++) {
                const int cb = col ^ (2 * (nf & 7));
                const uint2 q = *reinterpret_cast<const uint2*>(
                    &Vs[(nf * 8 + lrow) * ALDA + cb]);
                mma16(o[nf], a0, a1, a2, a3, q.x, q.y);
            }
        }

        __syncthreads();
        if (t + 1 < NT) {
            store_kv();
            __syncthreads();
        }
    }

    // Epilogue: x[b, s, h*64+d] = o / l  (half2 stores)
    const int b = bh >> 3, h = bh & 7;
#pragma unroll
    for (int hh = 0; hh < 2; hh++) {
        const int r = q0 + mrow + hh * 8;
        const float inv = 1.f / l_[hh];
#pragma unroll
        for (int nf = 0; nf < 8; nf++) {
            const int d = nf * 8 + 2 * lcol;
            *reinterpret_cast<uint32_t*>(
                &x[((size_t)(b * NS + r)) * NF + h * NDK + d]) =
                h2pack(o[nf][2 * hh + 0] * inv, o[nf][2 * hh + 1] * inv);
        }
    }
}

// ---------------------------------------------------------------------------
extern "C" void kernel_launch(void* const* d_in, const int* in_sizes, int n_in,
                              void* d_out, int out_size)
{
    const float* query = (const float*)d_in[0];
    // d_in[1] = key_t (unused by the synthesizer module)
    const float* value = (const float*)d_in[2];
    const float* w1 = (const float*)d_in[3];
    const float* b1 = (const float*)d_in[4];
    const float* w2 = (const float*)d_in[5];
    const float* b2 = (const float*)d_in[6];
    const float* wv = (const float*)d_in[7];
    const float* bv = (const float*)d_in[8];
    const float* wo = (const float*)d_in[9];
    const float* bo = (const float*)d_in[10];
    float* out = (float*)d_out;

    __half *qh, *valh, *w1h, *w2h, *wvh, *woh, *hh, *awh, *vh, *xh;
    cudaGetSymbolAddress((void**)&qh,   g_qh);
    cudaGetSymbolAddress((void**)&valh, g_valh);
    cudaGetSymbolAddress((void**)&w1h,  g_w1h);
    cudaGetSymbolAddress((void**)&w2h,  g_w2h);
    cudaGetSymbolAddress((void**)&wvh,  g_wvh);
    cudaGetSymbolAddress((void**)&woh,  g_woh);
    cudaGetSymbolAddress((void**)&hh,   g_hh);
    cudaGetSymbolAddress((void**)&awh,  g_awh);
    cudaGetSymbolAddress((void**)&vh,   g_vh);
    cudaGetSymbolAddress((void**)&xh,   g_xh);

    const dim3 blk(256);
    const int gemm_smem = 2 * 2 * 128 * GLDAH * 4;            // 49,152 B
    const int attn_smem = (128 + 64 + 64) * ALDA * 4;         // 40,960 B
    cudaFuncSetAttribute(hgemm<0>, cudaFuncAttributeMaxDynamicSharedMemorySize, gemm_smem);
    cudaFuncSetAttribute(hgemm<1>, cudaFuncAttributeMaxDynamicSharedMemorySize, gemm_smem);
    cudaFuncSetAttribute(hgemm<2>, cudaFuncAttributeMaxDynamicSharedMemorySize, gemm_smem);
    cudaFuncSetAttribute(attn_hmma, cudaFuncAttributeMaxDynamicSharedMemorySize, attn_smem);

    // 0) all fp32 -> fp16 conversions in ONE launch (9728 blocks)
    f2h_batch<<<9728, blk>>>(query, qh, value, valh, w1, w1h,
                             w2, w2h, wv, wvh, wo, woh);

    // 1) h = relu(q @ w1 + b1) -> half
    hgemm<0><<<dim3(NHID / 128, NM / 128), blk, gemm_smem>>>(NM, NHID, NF, qh, w1h, b1, hh);
    // 2) aw = h @ w2 + b2 -> half [B,H,S,dk]
    hgemm<1><<<dim3(NF / 128, NM / 128), blk, gemm_smem>>>(NM, NF, NHID, hh, w2h, b2, awh);
    // 3) v = value @ wv + bv -> half [B,H,S,dk]
    hgemm<1><<<dim3(NF / 128, NM / 128), blk, gemm_smem>>>(NM, NF, NF, valh, wvh, bv, vh);
    // 4) fp16 flash attention -> half x [B,S,F]
    attn_hmma<<<dim3(NS / 128, NB * NH), blk, attn_smem>>>(awh, vh, xh);
    // 5) out = x @ wo + bo -> float   (launch index 5: ncu -s 5 captures this)
    hgemm<2><<<dim3(NF / 128, NM / 128), blk, gemm_smem>>>(NM, NF, NF, xh, woh, bo, out);
}